// round 13
// baseline (speedup 1.0000x reference)
#include <cuda_runtime.h>
#include <cuda_bf16.h>
#include <cuda_fp16.h>
#include <math.h>
#include <stdint.h>

#define BATCH   1024
#define D_MODEL 4096
#define D_STATE 16
#define DT_RANK 256
#define XP_COLS (DT_RANK + 2 * D_STATE)   // 288
#define WXP_PAD 384                        // 288 padded to 3 x 128

// ---------------- scratch (allocation-free rule: __device__ globals) --------
__device__ float g_xp[BATCH * XP_COLS];
__device__ float g_delta[BATCH * D_MODEL];
__device__ uint16_t g_Wh16[(size_t)D_MODEL * D_MODEL];   // fp16(W_out)
__device__ uint16_t g_Yh[(size_t)BATCH * D_MODEL];       // fp16(ypre)
__device__ uint16_t g_xh[(size_t)BATCH * D_MODEL];       // bf16 hi(x)
__device__ uint16_t g_xl[(size_t)BATCH * D_MODEL];       // bf16 lo(x)
__device__ uint16_t g_Wxh[(size_t)WXP_PAD * D_MODEL];    // bf16 hi(W_xproj), padded
__device__ uint16_t g_Wxl[(size_t)WXP_PAD * D_MODEL];
__device__ uint16_t g_dh[(size_t)BATCH * DT_RANK];       // bf16 hi(delta_raw)
__device__ uint16_t g_dl[(size_t)BATCH * DT_RANK];
__device__ uint16_t g_Wdh[(size_t)D_MODEL * DT_RANK];    // bf16 hi(W_dt)
__device__ uint16_t g_Wdl[(size_t)D_MODEL * DT_RANK];

__device__ __forceinline__ float softplusf(float z) {
    return (z > 20.0f) ? z : log1pf(__expf(z));
}

// ---------------- PTX helpers (sm_80-class only; no 'a'-target features) ----
__device__ __forceinline__ uint32_t smem_u32(const void* p) {
    uint32_t a;
    asm("{ .reg .u64 t; cvta.to.shared.u64 t, %1; cvt.u32.u64 %0, t; }" : "=r"(a) : "l"(p));
    return a;
}
__device__ __forceinline__ void cpasync16(uint32_t dst, const void* src) {
    asm volatile("cp.async.cg.shared.global [%0], [%1], 16;" :: "r"(dst), "l"(src));
}
__device__ __forceinline__ void cpasync_commit() {
    asm volatile("cp.async.commit_group;" ::: "memory");
}
__device__ __forceinline__ void ldmatrix_x4(uint32_t* r, uint32_t addr) {
    asm volatile("ldmatrix.sync.aligned.m8n8.x4.shared.b16 {%0,%1,%2,%3}, [%4];"
                 : "=r"(r[0]), "=r"(r[1]), "=r"(r[2]), "=r"(r[3]) : "r"(addr));
}
// DT: 0 = bf16, 1 = fp16
template<int DT>
__device__ __forceinline__ void mma16(float* c, const uint32_t* a, const uint32_t* b) {
    if constexpr (DT == 0) {
        asm volatile(
            "mma.sync.aligned.m16n8k16.row.col.f32.bf16.bf16.f32 "
            "{%0,%1,%2,%3}, {%4,%5,%6,%7}, {%8,%9}, {%0,%1,%2,%3};"
            : "+f"(c[0]), "+f"(c[1]), "+f"(c[2]), "+f"(c[3])
            : "r"(a[0]), "r"(a[1]), "r"(a[2]), "r"(a[3]), "r"(b[0]), "r"(b[1]));
    } else {
        asm volatile(
            "mma.sync.aligned.m16n8k16.row.col.f32.f16.f16.f32 "
            "{%0,%1,%2,%3}, {%4,%5,%6,%7}, {%8,%9}, {%0,%1,%2,%3};"
            : "+f"(c[0]), "+f"(c[1]), "+f"(c[2]), "+f"(c[3])
            : "r"(a[0]), "r"(a[1]), "r"(a[2]), "r"(a[3]), "r"(b[0]), "r"(b[1]));
    }
}

// ---------------------------------------------------------------------------
// Conversion / split kernels
// ---------------------------------------------------------------------------
__global__ void zero_xp_kernel() {
    int i = blockIdx.x * blockDim.x + threadIdx.x;
    if (i < BATCH * XP_COLS) g_xp[i] = 0.0f;
}

__device__ __forceinline__ void split4_bf16(const float* vv, uint16_t* h, uint16_t* l, size_t i) {
    #pragma unroll
    for (int q = 0; q < 4; q++) {
        __nv_bfloat16 hi = __float2bfloat16(vv[q]);
        __nv_bfloat16 lo = __float2bfloat16(vv[q] - __bfloat162float(hi));
        h[i + q] = *(uint16_t*)&hi;
        l[i + q] = *(uint16_t*)&lo;
    }
}

__global__ void __launch_bounds__(256)
split_bf16_k(const float* __restrict__ in, uint16_t* __restrict__ h, uint16_t* __restrict__ l) {
    size_t i = ((size_t)blockIdx.x * blockDim.x + threadIdx.x) * 4;
    float4 v = *(const float4*)(in + i);
    float vv[4] = {v.x, v.y, v.z, v.w};
    split4_bf16(vv, h, l, i);
}

__global__ void __launch_bounds__(256)
conv_fp16_k(const float* __restrict__ in, uint16_t* __restrict__ out) {
    size_t i = ((size_t)blockIdx.x * blockDim.x + threadIdx.x) * 4;
    float4 v = *(const float4*)(in + i);
    __half h0 = __float2half_rn(v.x), h1 = __float2half_rn(v.y);
    __half h2 = __float2half_rn(v.z), h3 = __float2half_rn(v.w);
    uint16_t* o = out + i;
    o[0] = *(uint16_t*)&h0; o[1] = *(uint16_t*)&h1;
    o[2] = *(uint16_t*)&h2; o[3] = *(uint16_t*)&h3;
}

__global__ void __launch_bounds__(256)
split_wxproj_k(const float* __restrict__ in) {
    size_t i = ((size_t)blockIdx.x * blockDim.x + threadIdx.x) * 4;   // over 384*4096
    int row = (int)(i >> 12);
    float vv[4] = {0.f, 0.f, 0.f, 0.f};
    if (row < XP_COLS) {
        float4 v = *(const float4*)(in + i);
        vv[0] = v.x; vv[1] = v.y; vv[2] = v.z; vv[3] = v.w;
    }
    split4_bf16(vv, g_Wxh, g_Wxl, i);
}

__global__ void __launch_bounds__(256)
split_xp_k() {
    size_t i = ((size_t)blockIdx.x * blockDim.x + threadIdx.x) * 4;   // over 1024*256
    int row = (int)(i >> 8);
    int col = (int)(i & 255);
    float4 v = *(const float4*)(g_xp + (size_t)row * XP_COLS + col);
    float vv[4] = {v.x, v.y, v.z, v.w};
    split4_bf16(vv, g_dh, g_dl, i);
}

// ---------------------------------------------------------------------------
// Standalone fused state update (2 d per thread, MLP 8). b_off selects the
// batch half so it can be pipelined against G3 across streams.
// ---------------------------------------------------------------------------
__global__ void __launch_bounds__(256)
state_update(const float* __restrict__ x,
             const float* __restrict__ h,
             const float* __restrict__ A_log,
             const float* __restrict__ Dv,
             float* __restrict__ h_new,
             int b_off)
{
    __shared__ float sA[D_STATE], sB[D_STATE], sC[D_STATE];
    const int b = blockIdx.y + b_off;
    const int d0 = blockIdx.x * 512 + threadIdx.x;

    if (threadIdx.x < D_STATE) {
        int n = threadIdx.x;
        sA[n] = -expf(A_log[n]);
        sB[n] = g_xp[(size_t)b * XP_COLS + DT_RANK + n];
        sC[n] = g_xp[(size_t)b * XP_COLS + DT_RANK + D_STATE + n];
    }
    __syncthreads();

    const size_t bd0 = (size_t)b * D_MODEL + d0;
    const size_t bd1 = bd0 + 256;

    const float delta0 = g_delta[bd0];
    const float delta1 = g_delta[bd1];
    const float xv0 = x[bd0];
    const float xv1 = x[bd1];
    const float Dv0 = Dv[d0];
    const float Dv1 = Dv[d0 + 256];

    const float4* hp0 = (const float4*)(h + bd0 * D_STATE);
    const float4* hp1 = (const float4*)(h + bd1 * D_STATE);
    float4 hv0[4], hv1[4];
    #pragma unroll
    for (int q = 0; q < 4; q++) hv0[q] = hp0[q];
    #pragma unroll
    for (int q = 0; q < 4; q++) hv1[q] = hp1[q];

    float4* hop0 = (float4*)(h_new + bd0 * D_STATE);
    float4* hop1 = (float4*)(h_new + bd1 * D_STATE);

    const float dx0 = delta0 * xv0;
    const float dx1 = delta1 * xv1;
    float acc0 = 0.0f, acc1 = 0.0f;
    #pragma unroll
    for (int q = 0; q < 4; q++) {
        float a0 = sA[4 * q + 0], a1 = sA[4 * q + 1], a2 = sA[4 * q + 2], a3 = sA[4 * q + 3];
        float B0 = sB[4 * q + 0], B1 = sB[4 * q + 1], B2 = sB[4 * q + 2], B3 = sB[4 * q + 3];
        float C0 = sC[4 * q + 0], C1 = sC[4 * q + 1], C2 = sC[4 * q + 2], C3 = sC[4 * q + 3];

        float u0 = __expf(delta0 * a0) * hv0[q].x + dx0 * B0;
        float u1 = __expf(delta0 * a1) * hv0[q].y + dx0 * B1;
        float u2 = __expf(delta0 * a2) * hv0[q].z + dx0 * B2;
        float u3 = __expf(delta0 * a3) * hv0[q].w + dx0 * B3;
        acc0 += C0 * u0 + C1 * u1 + C2 * u2 + C3 * u3;
        hop0[q] = make_float4(u0, u1, u2, u3);

        float w0 = __expf(delta1 * a0) * hv1[q].x + dx1 * B0;
        float w1 = __expf(delta1 * a1) * hv1[q].y + dx1 * B1;
        float w2 = __expf(delta1 * a2) * hv1[q].z + dx1 * B2;
        float w3 = __expf(delta1 * a3) * hv1[q].w + dx1 * B3;
        acc1 += C0 * w0 + C1 * w1 + C2 * w2 + C3 * w3;
        hop1[q] = make_float4(w0, w1, w2, w3);
    }
    float yp0 = acc0 + Dv0 * xv0;
    float yp1 = acc1 + Dv1 * xv1;
    __half hh0 = __float2half_rn(yp0);
    __half hh1 = __float2half_rn(yp1);
    g_Yh[bd0] = *(uint16_t*)&hh0;
    g_Yh[bd1] = *(uint16_t*)&hh1;
}

// ---------------------------------------------------------------------------
// Unified HMMA GEMM (unchanged, measured-best configuration).
// ---------------------------------------------------------------------------
#define ROW_B 80
#define TILE_B (128 * ROW_B)          // 10240

template<int DT, bool ASPLIT, bool BSPLIT, int EPI, int NSTAGE, int OCC>
__global__ void __launch_bounds__(256, OCC)
gemm16(const uint16_t* __restrict__ Ah, const uint16_t* __restrict__ Al,
       const uint16_t* __restrict__ Bh, const uint16_t* __restrict__ Bl,
       float* __restrict__ C, int ldc, int ldab, int niters,
       const float* __restrict__ bias, int n_real)
{
    constexpr int NTILES = 1 + (ASPLIT ? 1 : 0) + 1 + (BSPLIT ? 1 : 0);
    constexpr uint32_t OFF_A0 = 0;
    constexpr uint32_t OFF_A1 = ASPLIT ? TILE_B : 0;
    constexpr uint32_t OFF_B0 = (ASPLIT ? 2 : 1) * TILE_B;
    constexpr uint32_t OFF_B1 = (ASPLIT ? 3 : 2) * TILE_B;   // only if BSPLIT
    constexpr uint32_t STAGE = NTILES * TILE_B;

    extern __shared__ char smem[];
    const uint32_t sb = smem_u32(smem);
    const int tid = threadIdx.x;
    const int wid = tid >> 5;
    const int lane = tid & 31;
    const int warp_m = wid >> 2;
    const int warp_n = wid & 3;
    const int bm = blockIdx.x * 128;
    const int bn = blockIdx.y * 128;
    const int k_begin = blockIdx.z * niters * 32;

    auto load_stage = [&](uint32_t st, int k0) {
        #pragma unroll
        for (int cc = 0; cc < 2; cc++) {
            const int idx = tid + 256 * cc;
            const int row = idx >> 2;
            const int ch  = idx & 3;
            const uint32_t d = st + (uint32_t)(row * ROW_B + ch * 16);
            const int gk = k0 + ch * 8;
            cpasync16(d + OFF_A0, Ah + (size_t)(bm + row) * ldab + gk);
            if constexpr (ASPLIT)
                cpasync16(d + OFF_A1, Al + (size_t)(bm + row) * ldab + gk);
            cpasync16(d + OFF_B0, Bh + (size_t)(bn + row) * ldab + gk);
            if constexpr (BSPLIT)
                cpasync16(d + OFF_B1, Bl + (size_t)(bn + row) * ldab + gk);
        }
        cpasync_commit();
    };

    // ldmatrix per-lane byte offsets (within a tile, ks=0)
    uint32_t aoff[4], boff[2];
    #pragma unroll
    for (int mi = 0; mi < 4; mi++)
        aoff[mi] = (uint32_t)((warp_m * 64 + mi * 16 + (lane & 15)) * ROW_B + (lane >> 4) * 16);
    #pragma unroll
    for (int pi = 0; pi < 2; pi++) {
        int chunk = lane >> 3;
        int n = warp_n * 32 + pi * 16 + (chunk >> 1) * 8 + (lane & 7);
        boff[pi] = (uint32_t)(n * ROW_B + (chunk & 1) * 16);
    }

    float acc[4][4][4];
    #pragma unroll
    for (int mi = 0; mi < 4; mi++)
        #pragma unroll
        for (int ni = 0; ni < 4; ni++)
            #pragma unroll
            for (int q = 0; q < 4; q++) acc[mi][ni][q] = 0.0f;

    // prologue: stages 0..NSTAGE-2
    #pragma unroll
    for (int s = 0; s < NSTAGE - 1; s++)
        load_stage(sb + s * STAGE, k_begin + s * 32);

    for (int it = 0; it < niters; it++) {
        if (it + NSTAGE - 1 < niters)
            load_stage(sb + ((it + NSTAGE - 1) % NSTAGE) * STAGE,
                       k_begin + (it + NSTAGE - 1) * 32);
        else
            cpasync_commit();   // keep group count uniform
        asm volatile("cp.async.wait_group %0;" :: "n"(NSTAGE - 1) : "memory");
        __syncthreads();

        const uint32_t st = sb + (it % NSTAGE) * STAGE;
        #pragma unroll
        for (int ks = 0; ks < 2; ks++) {
            uint32_t a0[4][4], a1[4][4], b0[2][4], b1[2][4];
            #pragma unroll
            for (int mi = 0; mi < 4; mi++) {
                ldmatrix_x4(a0[mi], st + OFF_A0 + aoff[mi] + ks * 32);
                if constexpr (ASPLIT)
                    ldmatrix_x4(a1[mi], st + OFF_A1 + aoff[mi] + ks * 32);
            }
            #pragma unroll
            for (int pi = 0; pi < 2; pi++) {
                ldmatrix_x4(b0[pi], st + OFF_B0 + boff[pi] + ks * 32);
                if constexpr (BSPLIT)
                    ldmatrix_x4(b1[pi], st + OFF_B1 + boff[pi] + ks * 32);
            }
            #pragma unroll
            for (int mi = 0; mi < 4; mi++) {
                #pragma unroll
                for (int ni = 0; ni < 4; ni++) {
                    const int pi = ni >> 1;
                    const int sel = (ni & 1) * 2;
                    uint32_t bh[2] = {b0[pi][sel], b0[pi][sel + 1]};
                    mma16<DT>(acc[mi][ni], a0[mi], bh);
                    if constexpr (ASPLIT)
                        mma16<DT>(acc[mi][ni], a1[mi], bh);
                    if constexpr (BSPLIT) {
                        uint32_t bl[2] = {b1[pi][sel], b1[pi][sel + 1]};
                        mma16<DT>(acc[mi][ni], a0[mi], bl);
                    }
                }
            }
        }
        __syncthreads();
    }

    // epilogue
    #pragma unroll
    for (int mi = 0; mi < 4; mi++) {
        const int row = bm + warp_m * 64 + mi * 16 + (lane >> 2);
        #pragma unroll
        for (int ni = 0; ni < 4; ni++) {
            const int col = bn + warp_n * 32 + ni * 8 + (lane & 3) * 2;
            float* acc4 = acc[mi][ni];
            if constexpr (EPI == 0) {
                *(float2*)(C + (size_t)row * ldc + col) = make_float2(acc4[0], acc4[1]);
                *(float2*)(C + (size_t)(row + 8) * ldc + col) = make_float2(acc4[2], acc4[3]);
            } else if constexpr (EPI == 1) {
                float b0v = bias[col], b1v = bias[col + 1];
                *(float2*)(C + (size_t)row * ldc + col) =
                    make_float2(softplusf(acc4[0] + b0v), softplusf(acc4[1] + b1v));
                *(float2*)(C + (size_t)(row + 8) * ldc + col) =
                    make_float2(softplusf(acc4[2] + b0v), softplusf(acc4[3] + b1v));
            } else {
                if (col < n_real) {   // col even, n_real even -> covers col+1
                    atomicAdd(&C[(size_t)row * ldc + col],       acc4[0]);
                    atomicAdd(&C[(size_t)row * ldc + col + 1],   acc4[1]);
                    atomicAdd(&C[(size_t)(row + 8) * ldc + col],     acc4[2]);
                    atomicAdd(&C[(size_t)(row + 8) * ldc + col + 1], acc4[3]);
                }
            }
        }
    }
}

// ---------------------------------------------------------------------------
// Launch. Inputs: x, h, W_xproj, W_dt, b_dt, A_log, D, W_out.
// Output: [y (1024*4096), h_new (1024*4096*16)].
// Stream fork/join: side stream hides W_out/W_dt conversion under G1 and
// pipelines G3(m-half0) against state_update(b-half1).
// ---------------------------------------------------------------------------
extern "C" void kernel_launch(void* const* d_in, const int* in_sizes, int n_in,
                              void* d_out, int out_size)
{
    const float* x    = (const float*)d_in[0];
    const float* h    = (const float*)d_in[1];
    const float* Wxp  = (const float*)d_in[2];
    const float* Wdt  = (const float*)d_in[3];
    const float* bdt  = (const float*)d_in[4];
    const float* Alog = (const float*)d_in[5];
    const float* Dv   = (const float*)d_in[6];
    const float* Wout = (const float*)d_in[7];

    float* y_out    = (float*)d_out;
    float* hnew_out = y_out + (size_t)BATCH * D_MODEL;

    float *xp_p, *delta_p;
    uint16_t *Wh16_p, *Yh_p, *xh_p, *xl_p, *Wxh_p, *Wxl_p, *dh_p, *dl_p, *Wdh_p, *Wdl_p;
    cudaGetSymbolAddress((void**)&xp_p, g_xp);
    cudaGetSymbolAddress((void**)&delta_p, g_delta);
    cudaGetSymbolAddress((void**)&Wh16_p, g_Wh16);
    cudaGetSymbolAddress((void**)&Yh_p, g_Yh);
    cudaGetSymbolAddress((void**)&xh_p, g_xh);
    cudaGetSymbolAddress((void**)&xl_p, g_xl);
    cudaGetSymbolAddress((void**)&Wxh_p, g_Wxh);
    cudaGetSymbolAddress((void**)&Wxl_p, g_Wxl);
    cudaGetSymbolAddress((void**)&dh_p, g_dh);
    cudaGetSymbolAddress((void**)&dl_p, g_dl);
    cudaGetSymbolAddress((void**)&Wdh_p, g_Wdh);
    cudaGetSymbolAddress((void**)&Wdl_p, g_Wdl);

    // One-time host-object creation (no device memory involved; GPU work is
    // identical on every call).
    static cudaStream_t s_side = nullptr;
    static cudaEvent_t eFork = nullptr, eWdt = nullptr, eS0 = nullptr, eG30 = nullptr;
    if (s_side == nullptr) {
        cudaStreamCreateWithFlags(&s_side, cudaStreamNonBlocking);
        cudaEventCreateWithFlags(&eFork, cudaEventDisableTiming);
        cudaEventCreateWithFlags(&eWdt, cudaEventDisableTiming);
        cudaEventCreateWithFlags(&eS0, cudaEventDisableTiming);
        cudaEventCreateWithFlags(&eG30, cudaEventDisableTiming);
    }

    const int SMEM4 = 2 * 4 * TILE_B;   // 81920  (bf16x3: 4 tiles, 2 stages)
    const int SMEM2 = 4 * 2 * TILE_B;   // 81920  (fp16x1: 2 tiles, 4 stages)
    cudaFuncSetAttribute((const void*)gemm16<0, true, true, 2, 2, 2>,
                         cudaFuncAttributeMaxDynamicSharedMemorySize, SMEM4);
    cudaFuncSetAttribute((const void*)gemm16<0, true, true, 1, 2, 2>,
                         cudaFuncAttributeMaxDynamicSharedMemorySize, SMEM4);
    cudaFuncSetAttribute((const void*)gemm16<1, false, false, 0, 4, 2>,
                         cudaFuncAttributeMaxDynamicSharedMemorySize, SMEM2);

    // ---- fork: side stream handles W_out/W_dt conversion ----
    cudaEventRecord(eFork, 0);
    cudaStreamWaitEvent(s_side, eFork, 0);
    conv_fp16_k<<<(D_MODEL * D_MODEL) / (4 * 256), 256, 0, s_side>>>(Wout, Wh16_p);
    split_bf16_k<<<(D_MODEL * DT_RANK) / (4 * 256), 256, 0, s_side>>>(Wdt, Wdh_p, Wdl_p);
    cudaEventRecord(eWdt, s_side);

    // ---- main stream: critical path ----
    split_bf16_k<<<(BATCH * D_MODEL) / (4 * 256), 256>>>(x, xh_p, xl_p);
    split_wxproj_k<<<(WXP_PAD * D_MODEL) / (4 * 256), 256>>>(Wxp);
    zero_xp_kernel<<<(BATCH * XP_COLS + 255) / 256, 256>>>();

    // G1: xp = x @ W_xproj^T  (bf16x3 HMMA, split-K=8, occ 2)
    gemm16<0, true, true, 2, 2, 2><<<dim3(BATCH / 128, WXP_PAD / 128, 8), 256, SMEM4>>>(
        xh_p, xl_p, Wxh_p, Wxl_p, xp_p, XP_COLS, D_MODEL, (D_MODEL / 8) / 32,
        nullptr, XP_COLS);

    split_xp_k<<<(BATCH * DT_RANK) / (4 * 256), 256>>>();

    // join: G2 needs W_dt split (side stream)
    cudaStreamWaitEvent(0, eWdt, 0);

    // G2: delta = softplus(delta_raw @ W_dt^T + b_dt)  (bf16x3, occ 2)
    gemm16<0, true, true, 1, 2, 2><<<dim3(BATCH / 128, D_MODEL / 128, 1), 256, SMEM4>>>(
        dh_p, dl_p, Wdh_p, Wdl_p, delta_p, D_MODEL, DT_RANK, DT_RANK / 32,
        bdt, D_MODEL);

    // state half 0 (b 0..511), then signal
    state_update<<<dim3(D_MODEL / 512, BATCH / 2), 256>>>(x, h, Alog, Dv, hnew_out, 0);
    cudaEventRecord(eS0, 0);

    // state half 1 (b 512..1023) on main, overlapped with G3 half 0 on side
    state_update<<<dim3(D_MODEL / 512, BATCH / 2), 256>>>(x, h, Alog, Dv, hnew_out, BATCH / 2);

    // side: G3 m-half 0 (rows 0..511) — needs state half 0 + Wh16 (same stream)
    cudaStreamWaitEvent(s_side, eS0, 0);
    gemm16<1, false, false, 0, 4, 2><<<dim3(BATCH / 256, D_MODEL / 128, 1), 256, SMEM2, s_side>>>(
        Yh_p, nullptr, Wh16_p, nullptr, y_out, D_MODEL, D_MODEL, D_MODEL / 32,
        nullptr, D_MODEL);
    cudaEventRecord(eG30, s_side);

    // main: G3 m-half 1 (rows 512..1023) — needs state half 1 (stream order)
    gemm16<1, false, false, 0, 4, 2><<<dim3(BATCH / 256, D_MODEL / 128, 1), 256, SMEM2>>>(
        Yh_p + (size_t)(BATCH / 2) * D_MODEL, nullptr, Wh16_p, nullptr,
        y_out + (size_t)(BATCH / 2) * D_MODEL, D_MODEL, D_MODEL, D_MODEL / 32,
        nullptr, D_MODEL);

    // final join
    cudaStreamWaitEvent(0, eG30, 0);
}

// round 14
// speedup vs baseline: 1.0071x; 1.0071x over previous
#include <cuda_runtime.h>
#include <cuda_bf16.h>
#include <cuda_fp16.h>
#include <math.h>
#include <stdint.h>

#define BATCH   1024
#define D_MODEL 4096
#define D_STATE 16
#define DT_RANK 256
#define XP_COLS (DT_RANK + 2 * D_STATE)   // 288
#define WXP_PAD 384                        // 288 padded to 3 x 128

// ---------------- scratch (allocation-free rule: __device__ globals) --------
__device__ float g_xp[BATCH * XP_COLS];
__device__ float g_delta[BATCH * D_MODEL];
__device__ uint16_t g_Wh16[(size_t)D_MODEL * D_MODEL];   // fp16(W_out)
__device__ uint16_t g_Yh[(size_t)BATCH * D_MODEL];       // fp16(ypre)
__device__ uint16_t g_xh[(size_t)BATCH * D_MODEL];       // bf16 hi(x)
__device__ uint16_t g_xl[(size_t)BATCH * D_MODEL];       // bf16 lo(x)
__device__ uint16_t g_Wxh[(size_t)WXP_PAD * D_MODEL];    // bf16 hi(W_xproj), padded
__device__ uint16_t g_Wxl[(size_t)WXP_PAD * D_MODEL];
__device__ uint16_t g_dh[(size_t)BATCH * DT_RANK];       // bf16 hi(delta_raw)
__device__ uint16_t g_dl[(size_t)BATCH * DT_RANK];
__device__ uint16_t g_Wdh[(size_t)D_MODEL * DT_RANK];    // bf16 hi(W_dt)
__device__ uint16_t g_Wdl[(size_t)D_MODEL * DT_RANK];

__device__ __forceinline__ float softplusf(float z) {
    return (z > 20.0f) ? z : log1pf(__expf(z));
}

// ---------------- PTX helpers (sm_80-class only; no 'a'-target features) ----
__device__ __forceinline__ uint32_t smem_u32(const void* p) {
    uint32_t a;
    asm("{ .reg .u64 t; cvta.to.shared.u64 t, %1; cvt.u32.u64 %0, t; }" : "=r"(a) : "l"(p));
    return a;
}
__device__ __forceinline__ void cpasync16(uint32_t dst, const void* src) {
    asm volatile("cp.async.cg.shared.global [%0], [%1], 16;" :: "r"(dst), "l"(src));
}
__device__ __forceinline__ void cpasync_commit() {
    asm volatile("cp.async.commit_group;" ::: "memory");
}
__device__ __forceinline__ void ldmatrix_x4(uint32_t* r, uint32_t addr) {
    asm volatile("ldmatrix.sync.aligned.m8n8.x4.shared.b16 {%0,%1,%2,%3}, [%4];"
                 : "=r"(r[0]), "=r"(r[1]), "=r"(r[2]), "=r"(r[3]) : "r"(addr));
}
// DT: 0 = bf16, 1 = fp16
template<int DT>
__device__ __forceinline__ void mma16(float* c, const uint32_t* a, const uint32_t* b) {
    if constexpr (DT == 0) {
        asm volatile(
            "mma.sync.aligned.m16n8k16.row.col.f32.bf16.bf16.f32 "
            "{%0,%1,%2,%3}, {%4,%5,%6,%7}, {%8,%9}, {%0,%1,%2,%3};"
            : "+f"(c[0]), "+f"(c[1]), "+f"(c[2]), "+f"(c[3])
            : "r"(a[0]), "r"(a[1]), "r"(a[2]), "r"(a[3]), "r"(b[0]), "r"(b[1]));
    } else {
        asm volatile(
            "mma.sync.aligned.m16n8k16.row.col.f32.f16.f16.f32 "
            "{%0,%1,%2,%3}, {%4,%5,%6,%7}, {%8,%9}, {%0,%1,%2,%3};"
            : "+f"(c[0]), "+f"(c[1]), "+f"(c[2]), "+f"(c[3])
            : "r"(a[0]), "r"(a[1]), "r"(a[2]), "r"(a[3]), "r"(b[0]), "r"(b[1]));
    }
}

// ---------------------------------------------------------------------------
// Conversion / split kernels
// ---------------------------------------------------------------------------
__global__ void zero_xp_kernel() {
    int i = blockIdx.x * blockDim.x + threadIdx.x;
    if (i < BATCH * XP_COLS) g_xp[i] = 0.0f;
}

__device__ __forceinline__ void split4_bf16(const float* vv, uint16_t* h, uint16_t* l, size_t i) {
    #pragma unroll
    for (int q = 0; q < 4; q++) {
        __nv_bfloat16 hi = __float2bfloat16(vv[q]);
        __nv_bfloat16 lo = __float2bfloat16(vv[q] - __bfloat162float(hi));
        h[i + q] = *(uint16_t*)&hi;
        l[i + q] = *(uint16_t*)&lo;
    }
}

__global__ void __launch_bounds__(256)
split_bf16_k(const float* __restrict__ in, uint16_t* __restrict__ h, uint16_t* __restrict__ l) {
    size_t i = ((size_t)blockIdx.x * blockDim.x + threadIdx.x) * 4;
    float4 v = *(const float4*)(in + i);
    float vv[4] = {v.x, v.y, v.z, v.w};
    split4_bf16(vv, h, l, i);
}

__global__ void __launch_bounds__(256)
conv_fp16_k(const float* __restrict__ in, uint16_t* __restrict__ out) {
    size_t i = ((size_t)blockIdx.x * blockDim.x + threadIdx.x) * 4;
    float4 v = *(const float4*)(in + i);
    __half h0 = __float2half_rn(v.x), h1 = __float2half_rn(v.y);
    __half h2 = __float2half_rn(v.z), h3 = __float2half_rn(v.w);
    uint16_t* o = out + i;
    o[0] = *(uint16_t*)&h0; o[1] = *(uint16_t*)&h1;
    o[2] = *(uint16_t*)&h2; o[3] = *(uint16_t*)&h3;
}

__global__ void __launch_bounds__(256)
split_wxproj_k(const float* __restrict__ in) {
    size_t i = ((size_t)blockIdx.x * blockDim.x + threadIdx.x) * 4;   // over 384*4096
    int row = (int)(i >> 12);
    float vv[4] = {0.f, 0.f, 0.f, 0.f};
    if (row < XP_COLS) {
        float4 v = *(const float4*)(in + i);
        vv[0] = v.x; vv[1] = v.y; vv[2] = v.z; vv[3] = v.w;
    }
    split4_bf16(vv, g_Wxh, g_Wxl, i);
}

__global__ void __launch_bounds__(256)
split_xp_k() {
    size_t i = ((size_t)blockIdx.x * blockDim.x + threadIdx.x) * 4;   // over 1024*256
    int row = (int)(i >> 8);
    int col = (int)(i & 255);
    float4 v = *(const float4*)(g_xp + (size_t)row * XP_COLS + col);
    float vv[4] = {v.x, v.y, v.z, v.w};
    split4_bf16(vv, g_dh, g_dl, i);
}

// ---------------------------------------------------------------------------
// Standalone fused state update (2 d per thread, MLP 8; full batch).
// ---------------------------------------------------------------------------
__global__ void __launch_bounds__(256)
state_update(const float* __restrict__ x,
             const float* __restrict__ h,
             const float* __restrict__ A_log,
             const float* __restrict__ Dv,
             float* __restrict__ h_new)
{
    __shared__ float sA[D_STATE], sB[D_STATE], sC[D_STATE];
    const int b = blockIdx.y;
    const int d0 = blockIdx.x * 512 + threadIdx.x;

    if (threadIdx.x < D_STATE) {
        int n = threadIdx.x;
        sA[n] = -expf(A_log[n]);
        sB[n] = g_xp[(size_t)b * XP_COLS + DT_RANK + n];
        sC[n] = g_xp[(size_t)b * XP_COLS + DT_RANK + D_STATE + n];
    }
    __syncthreads();

    const size_t bd0 = (size_t)b * D_MODEL + d0;
    const size_t bd1 = bd0 + 256;

    const float delta0 = g_delta[bd0];
    const float delta1 = g_delta[bd1];
    const float xv0 = x[bd0];
    const float xv1 = x[bd1];
    const float Dv0 = Dv[d0];
    const float Dv1 = Dv[d0 + 256];

    const float4* hp0 = (const float4*)(h + bd0 * D_STATE);
    const float4* hp1 = (const float4*)(h + bd1 * D_STATE);
    float4 hv0[4], hv1[4];
    #pragma unroll
    for (int q = 0; q < 4; q++) hv0[q] = hp0[q];
    #pragma unroll
    for (int q = 0; q < 4; q++) hv1[q] = hp1[q];

    float4* hop0 = (float4*)(h_new + bd0 * D_STATE);
    float4* hop1 = (float4*)(h_new + bd1 * D_STATE);

    const float dx0 = delta0 * xv0;
    const float dx1 = delta1 * xv1;
    float acc0 = 0.0f, acc1 = 0.0f;
    #pragma unroll
    for (int q = 0; q < 4; q++) {
        float a0 = sA[4 * q + 0], a1 = sA[4 * q + 1], a2 = sA[4 * q + 2], a3 = sA[4 * q + 3];
        float B0 = sB[4 * q + 0], B1 = sB[4 * q + 1], B2 = sB[4 * q + 2], B3 = sB[4 * q + 3];
        float C0 = sC[4 * q + 0], C1 = sC[4 * q + 1], C2 = sC[4 * q + 2], C3 = sC[4 * q + 3];

        float u0 = __expf(delta0 * a0) * hv0[q].x + dx0 * B0;
        float u1 = __expf(delta0 * a1) * hv0[q].y + dx0 * B1;
        float u2 = __expf(delta0 * a2) * hv0[q].z + dx0 * B2;
        float u3 = __expf(delta0 * a3) * hv0[q].w + dx0 * B3;
        acc0 += C0 * u0 + C1 * u1 + C2 * u2 + C3 * u3;
        hop0[q] = make_float4(u0, u1, u2, u3);

        float w0 = __expf(delta1 * a0) * hv1[q].x + dx1 * B0;
        float w1 = __expf(delta1 * a1) * hv1[q].y + dx1 * B1;
        float w2 = __expf(delta1 * a2) * hv1[q].z + dx1 * B2;
        float w3 = __expf(delta1 * a3) * hv1[q].w + dx1 * B3;
        acc1 += C0 * w0 + C1 * w1 + C2 * w2 + C3 * w3;
        hop1[q] = make_float4(w0, w1, w2, w3);
    }
    float yp0 = acc0 + Dv0 * xv0;
    float yp1 = acc1 + Dv1 * xv1;
    __half hh0 = __float2half_rn(yp0);
    __half hh1 = __float2half_rn(yp1);
    g_Yh[bd0] = *(uint16_t*)&hh0;
    g_Yh[bd1] = *(uint16_t*)&hh1;
}

// ---------------------------------------------------------------------------
// Unified HMMA GEMM (measured-best configuration).
// ---------------------------------------------------------------------------
#define ROW_B 80
#define TILE_B (128 * ROW_B)          // 10240

template<int DT, bool ASPLIT, bool BSPLIT, int EPI, int NSTAGE, int OCC>
__global__ void __launch_bounds__(256, OCC)
gemm16(const uint16_t* __restrict__ Ah, const uint16_t* __restrict__ Al,
       const uint16_t* __restrict__ Bh, const uint16_t* __restrict__ Bl,
       float* __restrict__ C, int ldc, int ldab, int niters,
       const float* __restrict__ bias, int n_real)
{
    constexpr int NTILES = 1 + (ASPLIT ? 1 : 0) + 1 + (BSPLIT ? 1 : 0);
    constexpr uint32_t OFF_A0 = 0;
    constexpr uint32_t OFF_A1 = ASPLIT ? TILE_B : 0;
    constexpr uint32_t OFF_B0 = (ASPLIT ? 2 : 1) * TILE_B;
    constexpr uint32_t OFF_B1 = (ASPLIT ? 3 : 2) * TILE_B;   // only if BSPLIT
    constexpr uint32_t STAGE = NTILES * TILE_B;

    extern __shared__ char smem[];
    const uint32_t sb = smem_u32(smem);
    const int tid = threadIdx.x;
    const int wid = tid >> 5;
    const int lane = tid & 31;
    const int warp_m = wid >> 2;
    const int warp_n = wid & 3;
    const int bm = blockIdx.x * 128;
    const int bn = blockIdx.y * 128;
    const int k_begin = blockIdx.z * niters * 32;

    auto load_stage = [&](uint32_t st, int k0) {
        #pragma unroll
        for (int cc = 0; cc < 2; cc++) {
            const int idx = tid + 256 * cc;
            const int row = idx >> 2;
            const int ch  = idx & 3;
            const uint32_t d = st + (uint32_t)(row * ROW_B + ch * 16);
            const int gk = k0 + ch * 8;
            cpasync16(d + OFF_A0, Ah + (size_t)(bm + row) * ldab + gk);
            if constexpr (ASPLIT)
                cpasync16(d + OFF_A1, Al + (size_t)(bm + row) * ldab + gk);
            cpasync16(d + OFF_B0, Bh + (size_t)(bn + row) * ldab + gk);
            if constexpr (BSPLIT)
                cpasync16(d + OFF_B1, Bl + (size_t)(bn + row) * ldab + gk);
        }
        cpasync_commit();
    };

    // ldmatrix per-lane byte offsets (within a tile, ks=0)
    uint32_t aoff[4], boff[2];
    #pragma unroll
    for (int mi = 0; mi < 4; mi++)
        aoff[mi] = (uint32_t)((warp_m * 64 + mi * 16 + (lane & 15)) * ROW_B + (lane >> 4) * 16);
    #pragma unroll
    for (int pi = 0; pi < 2; pi++) {
        int chunk = lane >> 3;
        int n = warp_n * 32 + pi * 16 + (chunk >> 1) * 8 + (lane & 7);
        boff[pi] = (uint32_t)(n * ROW_B + (chunk & 1) * 16);
    }

    float acc[4][4][4];
    #pragma unroll
    for (int mi = 0; mi < 4; mi++)
        #pragma unroll
        for (int ni = 0; ni < 4; ni++)
            #pragma unroll
            for (int q = 0; q < 4; q++) acc[mi][ni][q] = 0.0f;

    // prologue: stages 0..NSTAGE-2
    #pragma unroll
    for (int s = 0; s < NSTAGE - 1; s++)
        load_stage(sb + s * STAGE, k_begin + s * 32);

    for (int it = 0; it < niters; it++) {
        if (it + NSTAGE - 1 < niters)
            load_stage(sb + ((it + NSTAGE - 1) % NSTAGE) * STAGE,
                       k_begin + (it + NSTAGE - 1) * 32);
        else
            cpasync_commit();   // keep group count uniform
        asm volatile("cp.async.wait_group %0;" :: "n"(NSTAGE - 1) : "memory");
        __syncthreads();

        const uint32_t st = sb + (it % NSTAGE) * STAGE;
        #pragma unroll
        for (int ks = 0; ks < 2; ks++) {
            uint32_t a0[4][4], a1[4][4], b0[2][4], b1[2][4];
            #pragma unroll
            for (int mi = 0; mi < 4; mi++) {
                ldmatrix_x4(a0[mi], st + OFF_A0 + aoff[mi] + ks * 32);
                if constexpr (ASPLIT)
                    ldmatrix_x4(a1[mi], st + OFF_A1 + aoff[mi] + ks * 32);
            }
            #pragma unroll
            for (int pi = 0; pi < 2; pi++) {
                ldmatrix_x4(b0[pi], st + OFF_B0 + boff[pi] + ks * 32);
                if constexpr (BSPLIT)
                    ldmatrix_x4(b1[pi], st + OFF_B1 + boff[pi] + ks * 32);
            }
            #pragma unroll
            for (int mi = 0; mi < 4; mi++) {
                #pragma unroll
                for (int ni = 0; ni < 4; ni++) {
                    const int pi = ni >> 1;
                    const int sel = (ni & 1) * 2;
                    uint32_t bh[2] = {b0[pi][sel], b0[pi][sel + 1]};
                    mma16<DT>(acc[mi][ni], a0[mi], bh);
                    if constexpr (ASPLIT)
                        mma16<DT>(acc[mi][ni], a1[mi], bh);
                    if constexpr (BSPLIT) {
                        uint32_t bl[2] = {b1[pi][sel], b1[pi][sel + 1]};
                        mma16<DT>(acc[mi][ni], a0[mi], bl);
                    }
                }
            }
        }
        __syncthreads();
    }

    // epilogue
    #pragma unroll
    for (int mi = 0; mi < 4; mi++) {
        const int row = bm + warp_m * 64 + mi * 16 + (lane >> 2);
        #pragma unroll
        for (int ni = 0; ni < 4; ni++) {
            const int col = bn + warp_n * 32 + ni * 8 + (lane & 3) * 2;
            float* acc4 = acc[mi][ni];
            if constexpr (EPI == 0) {
                *(float2*)(C + (size_t)row * ldc + col) = make_float2(acc4[0], acc4[1]);
                *(float2*)(C + (size_t)(row + 8) * ldc + col) = make_float2(acc4[2], acc4[3]);
            } else if constexpr (EPI == 1) {
                float b0v = bias[col], b1v = bias[col + 1];
                *(float2*)(C + (size_t)row * ldc + col) =
                    make_float2(softplusf(acc4[0] + b0v), softplusf(acc4[1] + b1v));
                *(float2*)(C + (size_t)(row + 8) * ldc + col) =
                    make_float2(softplusf(acc4[2] + b0v), softplusf(acc4[3] + b1v));
            } else {
                if (col < n_real) {   // col even, n_real even -> covers col+1
                    atomicAdd(&C[(size_t)row * ldc + col],       acc4[0]);
                    atomicAdd(&C[(size_t)row * ldc + col + 1],   acc4[1]);
                    atomicAdd(&C[(size_t)(row + 8) * ldc + col],     acc4[2]);
                    atomicAdd(&C[(size_t)(row + 8) * ldc + col + 1], acc4[3]);
                }
            }
        }
    }
}

// ---------------------------------------------------------------------------
// Launch. Inputs: x, h, W_xproj, W_dt, b_dt, A_log, D, W_out.
// Output: [y (1024*4096), h_new (1024*4096*16)].
// ---------------------------------------------------------------------------
extern "C" void kernel_launch(void* const* d_in, const int* in_sizes, int n_in,
                              void* d_out, int out_size)
{
    const float* x    = (const float*)d_in[0];
    const float* h    = (const float*)d_in[1];
    const float* Wxp  = (const float*)d_in[2];
    const float* Wdt  = (const float*)d_in[3];
    const float* bdt  = (const float*)d_in[4];
    const float* Alog = (const float*)d_in[5];
    const float* Dv   = (const float*)d_in[6];
    const float* Wout = (const float*)d_in[7];

    float* y_out    = (float*)d_out;
    float* hnew_out = y_out + (size_t)BATCH * D_MODEL;

    float *xp_p, *delta_p;
    uint16_t *Wh16_p, *Yh_p, *xh_p, *xl_p, *Wxh_p, *Wxl_p, *dh_p, *dl_p, *Wdh_p, *Wdl_p;
    cudaGetSymbolAddress((void**)&xp_p, g_xp);
    cudaGetSymbolAddress((void**)&delta_p, g_delta);
    cudaGetSymbolAddress((void**)&Wh16_p, g_Wh16);
    cudaGetSymbolAddress((void**)&Yh_p, g_Yh);
    cudaGetSymbolAddress((void**)&xh_p, g_xh);
    cudaGetSymbolAddress((void**)&xl_p, g_xl);
    cudaGetSymbolAddress((void**)&Wxh_p, g_Wxh);
    cudaGetSymbolAddress((void**)&Wxl_p, g_Wxl);
    cudaGetSymbolAddress((void**)&dh_p, g_dh);
    cudaGetSymbolAddress((void**)&dl_p, g_dl);
    cudaGetSymbolAddress((void**)&Wdh_p, g_Wdh);
    cudaGetSymbolAddress((void**)&Wdl_p, g_Wdl);

    // One-time host-object creation (no device memory; identical GPU work per call)
    static cudaStream_t s_side = nullptr;
    static cudaEvent_t eFork = nullptr, eWdt = nullptr;
    if (s_side == nullptr) {
        cudaStreamCreateWithFlags(&s_side, cudaStreamNonBlocking);
        cudaEventCreateWithFlags(&eFork, cudaEventDisableTiming);
        cudaEventCreateWithFlags(&eWdt, cudaEventDisableTiming);
    }

    const int SMEM4 = 2 * 4 * TILE_B;   // 81920  (bf16x3: 4 tiles, 2 stages)
    const int SMEM2 = 4 * 2 * TILE_B;   // 81920  (fp16x1: 2 tiles, 4 stages)
    cudaFuncSetAttribute((const void*)gemm16<0, true, true, 2, 2, 2>,
                         cudaFuncAttributeMaxDynamicSharedMemorySize, SMEM4);
    cudaFuncSetAttribute((const void*)gemm16<0, true, true, 1, 2, 2>,
                         cudaFuncAttributeMaxDynamicSharedMemorySize, SMEM4);
    cudaFuncSetAttribute((const void*)gemm16<1, false, false, 0, 4, 2>,
                         cudaFuncAttributeMaxDynamicSharedMemorySize, SMEM2);

    // ---- fork: side stream converts W_out (for G3) and W_dt (for G2) ----
    cudaEventRecord(eFork, 0);
    cudaStreamWaitEvent(s_side, eFork, 0);
    conv_fp16_k<<<(D_MODEL * D_MODEL) / (4 * 256), 256, 0, s_side>>>(Wout, Wh16_p);
    split_bf16_k<<<(D_MODEL * DT_RANK) / (4 * 256), 256, 0, s_side>>>(Wdt, Wdh_p, Wdl_p);
    cudaEventRecord(eWdt, s_side);

    // ---- main stream: critical path ----
    split_bf16_k<<<(BATCH * D_MODEL) / (4 * 256), 256>>>(x, xh_p, xl_p);
    split_wxproj_k<<<(WXP_PAD * D_MODEL) / (4 * 256), 256>>>(Wxp);
    zero_xp_kernel<<<(BATCH * XP_COLS + 255) / 256, 256>>>();

    // G1: xp = x @ W_xproj^T  (bf16x3 HMMA, split-K=16 -> 384 CTAs, occ 2)
    gemm16<0, true, true, 2, 2, 2><<<dim3(BATCH / 128, WXP_PAD / 128, 16), 256, SMEM4>>>(
        xh_p, xl_p, Wxh_p, Wxl_p, xp_p, XP_COLS, D_MODEL, (D_MODEL / 16) / 32,
        nullptr, XP_COLS);

    // delta_raw split (xp cols 0..255 -> bf16 hi/lo)
    split_xp_k<<<(BATCH * DT_RANK) / (4 * 256), 256>>>();

    // join: G2 needs W_dt split from side stream
    cudaStreamWaitEvent(0, eWdt, 0);

    // G2: delta = softplus(delta_raw @ W_dt^T + b_dt)  (bf16x3, occ 2)
    gemm16<0, true, true, 1, 2, 2><<<dim3(BATCH / 128, D_MODEL / 128, 1), 256, SMEM4>>>(
        dh_p, dl_p, Wdh_p, Wdl_p, delta_p, D_MODEL, DT_RANK, DT_RANK / 32,
        bdt, D_MODEL);

    // Standalone state update (full batch; 2 d per thread)
    state_update<<<dim3(D_MODEL / 512, BATCH), 256>>>(x, h, Alog, Dv, hnew_out);

    // G3: y = fp16(ypre) @ fp16(W_out)^T  (single product, 4-stage, occ 2)
    gemm16<1, false, false, 0, 4, 2><<<dim3(BATCH / 128, D_MODEL / 128, 1), 256, SMEM2>>>(
        Yh_p, nullptr, Wh16_p, nullptr, y_out, D_MODEL, D_MODEL, D_MODEL / 32,
        nullptr, D_MODEL);
}

// round 15
// speedup vs baseline: 1.0080x; 1.0009x over previous
#include <cuda_runtime.h>
#include <cuda_bf16.h>
#include <cuda_fp16.h>
#include <math.h>
#include <stdint.h>

#define BATCH   1024
#define D_MODEL 4096
#define D_STATE 16
#define DT_RANK 256
#define XP_COLS (DT_RANK + 2 * D_STATE)   // 288
#define WXP_PAD 384                        // 288 padded to 3 x 128

// ---------------- scratch (allocation-free rule: __device__ globals) --------
__device__ float g_xp[BATCH * XP_COLS];
__device__ float g_delta[BATCH * D_MODEL];
__device__ uint16_t g_Wh16[(size_t)D_MODEL * D_MODEL];   // fp16(W_out)
__device__ uint16_t g_Yh[(size_t)BATCH * D_MODEL];       // fp16(ypre)
__device__ uint16_t g_xh[(size_t)BATCH * D_MODEL];       // bf16 hi(x)
__device__ uint16_t g_xl[(size_t)BATCH * D_MODEL];       // bf16 lo(x)
__device__ uint16_t g_Wxh[(size_t)WXP_PAD * D_MODEL];    // bf16 hi(W_xproj), padded
__device__ uint16_t g_Wxl[(size_t)WXP_PAD * D_MODEL];
__device__ uint16_t g_dh[(size_t)BATCH * DT_RANK];       // bf16 hi(delta_raw)
__device__ uint16_t g_dl[(size_t)BATCH * DT_RANK];
__device__ uint16_t g_Wdh[(size_t)D_MODEL * DT_RANK];    // bf16 hi(W_dt)
__device__ uint16_t g_Wdl[(size_t)D_MODEL * DT_RANK];

__device__ __forceinline__ float softplusf(float z) {
    return (z > 20.0f) ? z : log1pf(__expf(z));
}

// ---------------- PTX helpers (sm_80-class only; no 'a'-target features) ----
__device__ __forceinline__ uint32_t smem_u32(const void* p) {
    uint32_t a;
    asm("{ .reg .u64 t; cvta.to.shared.u64 t, %1; cvt.u32.u64 %0, t; }" : "=r"(a) : "l"(p));
    return a;
}
__device__ __forceinline__ void cpasync16(uint32_t dst, const void* src) {
    asm volatile("cp.async.cg.shared.global [%0], [%1], 16;" :: "r"(dst), "l"(src));
}
__device__ __forceinline__ void cpasync_commit() {
    asm volatile("cp.async.commit_group;" ::: "memory");
}
__device__ __forceinline__ void ldmatrix_x4(uint32_t* r, uint32_t addr) {
    asm volatile("ldmatrix.sync.aligned.m8n8.x4.shared.b16 {%0,%1,%2,%3}, [%4];"
                 : "=r"(r[0]), "=r"(r[1]), "=r"(r[2]), "=r"(r[3]) : "r"(addr));
}
// DT: 0 = bf16, 1 = fp16
template<int DT>
__device__ __forceinline__ void mma16(float* c, const uint32_t* a, const uint32_t* b) {
    if constexpr (DT == 0) {
        asm volatile(
            "mma.sync.aligned.m16n8k16.row.col.f32.bf16.bf16.f32 "
            "{%0,%1,%2,%3}, {%4,%5,%6,%7}, {%8,%9}, {%0,%1,%2,%3};"
            : "+f"(c[0]), "+f"(c[1]), "+f"(c[2]), "+f"(c[3])
            : "r"(a[0]), "r"(a[1]), "r"(a[2]), "r"(a[3]), "r"(b[0]), "r"(b[1]));
    } else {
        asm volatile(
            "mma.sync.aligned.m16n8k16.row.col.f32.f16.f16.f32 "
            "{%0,%1,%2,%3}, {%4,%5,%6,%7}, {%8,%9}, {%0,%1,%2,%3};"
            : "+f"(c[0]), "+f"(c[1]), "+f"(c[2]), "+f"(c[3])
            : "r"(a[0]), "r"(a[1]), "r"(a[2]), "r"(a[3]), "r"(b[0]), "r"(b[1]));
    }
}

// ---------------------------------------------------------------------------
// Conversion / split kernels
// ---------------------------------------------------------------------------
__device__ __forceinline__ void split4_bf16(const float* vv, uint16_t* h, uint16_t* l, size_t i) {
    #pragma unroll
    for (int q = 0; q < 4; q++) {
        __nv_bfloat16 hi = __float2bfloat16(vv[q]);
        __nv_bfloat16 lo = __float2bfloat16(vv[q] - __bfloat162float(hi));
        h[i + q] = *(uint16_t*)&hi;
        l[i + q] = *(uint16_t*)&lo;
    }
}

__global__ void __launch_bounds__(256)
split_bf16_k(const float* __restrict__ in, uint16_t* __restrict__ h, uint16_t* __restrict__ l) {
    size_t i = ((size_t)blockIdx.x * blockDim.x + threadIdx.x) * 4;
    float4 v = *(const float4*)(in + i);
    float vv[4] = {v.x, v.y, v.z, v.w};
    split4_bf16(vv, h, l, i);
}

__global__ void __launch_bounds__(256)
conv_fp16_k(const float* __restrict__ in, uint16_t* __restrict__ out) {
    size_t i = ((size_t)blockIdx.x * blockDim.x + threadIdx.x) * 4;
    float4 v = *(const float4*)(in + i);
    __half h0 = __float2half_rn(v.x), h1 = __float2half_rn(v.y);
    __half h2 = __float2half_rn(v.z), h3 = __float2half_rn(v.w);
    uint16_t* o = out + i;
    o[0] = *(uint16_t*)&h0; o[1] = *(uint16_t*)&h1;
    o[2] = *(uint16_t*)&h2; o[3] = *(uint16_t*)&h3;
}

// W_xproj split (padded to 384 rows) + zero of g_xp, one launch.
// Slots: [0, N2) = wxproj float4 slots, [N2, N2+N4) = g_xp zero slots.
#define PREP_N2 ((size_t)WXP_PAD * D_MODEL / 4)     // 393216
#define PREP_N4 ((size_t)BATCH * XP_COLS / 4)       // 73728
__global__ void __launch_bounds__(256)
split_wxproj_zero_k(const float* __restrict__ in) {
    size_t gid = (size_t)blockIdx.x * 256 + threadIdx.x;
    if (gid < PREP_N2) {
        size_t i = gid * 4;
        int row = (int)(i >> 12);
        float vv[4] = {0.f, 0.f, 0.f, 0.f};
        if (row < XP_COLS) {
            float4 v = *(const float4*)(in + i);
            vv[0] = v.x; vv[1] = v.y; vv[2] = v.z; vv[3] = v.w;
        }
        split4_bf16(vv, g_Wxh, g_Wxl, i);
    } else {
        size_t i = (gid - PREP_N2) * 4;
        *(float4*)(g_xp + i) = make_float4(0.f, 0.f, 0.f, 0.f);
    }
}

__global__ void __launch_bounds__(256)
split_xp_k() {
    size_t i = ((size_t)blockIdx.x * blockDim.x + threadIdx.x) * 4;   // over 1024*256
    int row = (int)(i >> 8);
    int col = (int)(i & 255);
    float4 v = *(const float4*)(g_xp + (size_t)row * XP_COLS + col);
    float vv[4] = {v.x, v.y, v.z, v.w};
    split4_bf16(vv, g_dh, g_dl, i);
}

// ---------------------------------------------------------------------------
// Standalone fused state update (2 d per thread, MLP 8; full batch).
// ---------------------------------------------------------------------------
__global__ void __launch_bounds__(256)
state_update(const float* __restrict__ x,
             const float* __restrict__ h,
             const float* __restrict__ A_log,
             const float* __restrict__ Dv,
             float* __restrict__ h_new)
{
    __shared__ float sA[D_STATE], sB[D_STATE], sC[D_STATE];
    const int b = blockIdx.y;
    const int d0 = blockIdx.x * 512 + threadIdx.x;

    if (threadIdx.x < D_STATE) {
        int n = threadIdx.x;
        sA[n] = -expf(A_log[n]);
        sB[n] = g_xp[(size_t)b * XP_COLS + DT_RANK + n];
        sC[n] = g_xp[(size_t)b * XP_COLS + DT_RANK + D_STATE + n];
    }
    __syncthreads();

    const size_t bd0 = (size_t)b * D_MODEL + d0;
    const size_t bd1 = bd0 + 256;

    const float delta0 = g_delta[bd0];
    const float delta1 = g_delta[bd1];
    const float xv0 = x[bd0];
    const float xv1 = x[bd1];
    const float Dv0 = Dv[d0];
    const float Dv1 = Dv[d0 + 256];

    const float4* hp0 = (const float4*)(h + bd0 * D_STATE);
    const float4* hp1 = (const float4*)(h + bd1 * D_STATE);
    float4 hv0[4], hv1[4];
    #pragma unroll
    for (int q = 0; q < 4; q++) hv0[q] = hp0[q];
    #pragma unroll
    for (int q = 0; q < 4; q++) hv1[q] = hp1[q];

    float4* hop0 = (float4*)(h_new + bd0 * D_STATE);
    float4* hop1 = (float4*)(h_new + bd1 * D_STATE);

    const float dx0 = delta0 * xv0;
    const float dx1 = delta1 * xv1;
    float acc0 = 0.0f, acc1 = 0.0f;
    #pragma unroll
    for (int q = 0; q < 4; q++) {
        float a0 = sA[4 * q + 0], a1 = sA[4 * q + 1], a2 = sA[4 * q + 2], a3 = sA[4 * q + 3];
        float B0 = sB[4 * q + 0], B1 = sB[4 * q + 1], B2 = sB[4 * q + 2], B3 = sB[4 * q + 3];
        float C0 = sC[4 * q + 0], C1 = sC[4 * q + 1], C2 = sC[4 * q + 2], C3 = sC[4 * q + 3];

        float u0 = __expf(delta0 * a0) * hv0[q].x + dx0 * B0;
        float u1 = __expf(delta0 * a1) * hv0[q].y + dx0 * B1;
        float u2 = __expf(delta0 * a2) * hv0[q].z + dx0 * B2;
        float u3 = __expf(delta0 * a3) * hv0[q].w + dx0 * B3;
        acc0 += C0 * u0 + C1 * u1 + C2 * u2 + C3 * u3;
        hop0[q] = make_float4(u0, u1, u2, u3);

        float w0 = __expf(delta1 * a0) * hv1[q].x + dx1 * B0;
        float w1 = __expf(delta1 * a1) * hv1[q].y + dx1 * B1;
        float w2 = __expf(delta1 * a2) * hv1[q].z + dx1 * B2;
        float w3 = __expf(delta1 * a3) * hv1[q].w + dx1 * B3;
        acc1 += C0 * w0 + C1 * w1 + C2 * w2 + C3 * w3;
        hop1[q] = make_float4(w0, w1, w2, w3);
    }
    float yp0 = acc0 + Dv0 * xv0;
    float yp1 = acc1 + Dv1 * xv1;
    __half hh0 = __float2half_rn(yp0);
    __half hh1 = __float2half_rn(yp1);
    g_Yh[bd0] = *(uint16_t*)&hh0;
    g_Yh[bd1] = *(uint16_t*)&hh1;
}

// ---------------------------------------------------------------------------
// Unified HMMA GEMM (measured-best configuration).
// ---------------------------------------------------------------------------
#define ROW_B 80
#define TILE_B (128 * ROW_B)          // 10240

template<int DT, bool ASPLIT, bool BSPLIT, int EPI, int NSTAGE, int OCC>
__global__ void __launch_bounds__(256, OCC)
gemm16(const uint16_t* __restrict__ Ah, const uint16_t* __restrict__ Al,
       const uint16_t* __restrict__ Bh, const uint16_t* __restrict__ Bl,
       float* __restrict__ C, int ldc, int ldab, int niters,
       const float* __restrict__ bias, int n_real)
{
    constexpr int NTILES = 1 + (ASPLIT ? 1 : 0) + 1 + (BSPLIT ? 1 : 0);
    constexpr uint32_t OFF_A0 = 0;
    constexpr uint32_t OFF_A1 = ASPLIT ? TILE_B : 0;
    constexpr uint32_t OFF_B0 = (ASPLIT ? 2 : 1) * TILE_B;
    constexpr uint32_t OFF_B1 = (ASPLIT ? 3 : 2) * TILE_B;   // only if BSPLIT
    constexpr uint32_t STAGE = NTILES * TILE_B;

    extern __shared__ char smem[];
    const uint32_t sb = smem_u32(smem);
    const int tid = threadIdx.x;
    const int wid = tid >> 5;
    const int lane = tid & 31;
    const int warp_m = wid >> 2;
    const int warp_n = wid & 3;
    const int bm = blockIdx.x * 128;
    const int bn = blockIdx.y * 128;
    const int k_begin = blockIdx.z * niters * 32;

    auto load_stage = [&](uint32_t st, int k0) {
        #pragma unroll
        for (int cc = 0; cc < 2; cc++) {
            const int idx = tid + 256 * cc;
            const int row = idx >> 2;
            const int ch  = idx & 3;
            const uint32_t d = st + (uint32_t)(row * ROW_B + ch * 16);
            const int gk = k0 + ch * 8;
            cpasync16(d + OFF_A0, Ah + (size_t)(bm + row) * ldab + gk);
            if constexpr (ASPLIT)
                cpasync16(d + OFF_A1, Al + (size_t)(bm + row) * ldab + gk);
            cpasync16(d + OFF_B0, Bh + (size_t)(bn + row) * ldab + gk);
            if constexpr (BSPLIT)
                cpasync16(d + OFF_B1, Bl + (size_t)(bn + row) * ldab + gk);
        }
        cpasync_commit();
    };

    // ldmatrix per-lane byte offsets (within a tile, ks=0)
    uint32_t aoff[4], boff[2];
    #pragma unroll
    for (int mi = 0; mi < 4; mi++)
        aoff[mi] = (uint32_t)((warp_m * 64 + mi * 16 + (lane & 15)) * ROW_B + (lane >> 4) * 16);
    #pragma unroll
    for (int pi = 0; pi < 2; pi++) {
        int chunk = lane >> 3;
        int n = warp_n * 32 + pi * 16 + (chunk >> 1) * 8 + (lane & 7);
        boff[pi] = (uint32_t)(n * ROW_B + (chunk & 1) * 16);
    }

    float acc[4][4][4];
    #pragma unroll
    for (int mi = 0; mi < 4; mi++)
        #pragma unroll
        for (int ni = 0; ni < 4; ni++)
            #pragma unroll
            for (int q = 0; q < 4; q++) acc[mi][ni][q] = 0.0f;

    // prologue: stages 0..NSTAGE-2
    #pragma unroll
    for (int s = 0; s < NSTAGE - 1; s++)
        load_stage(sb + s * STAGE, k_begin + s * 32);

    for (int it = 0; it < niters; it++) {
        if (it + NSTAGE - 1 < niters)
            load_stage(sb + ((it + NSTAGE - 1) % NSTAGE) * STAGE,
                       k_begin + (it + NSTAGE - 1) * 32);
        else
            cpasync_commit();   // keep group count uniform
        asm volatile("cp.async.wait_group %0;" :: "n"(NSTAGE - 1) : "memory");
        __syncthreads();

        const uint32_t st = sb + (it % NSTAGE) * STAGE;
        #pragma unroll
        for (int ks = 0; ks < 2; ks++) {
            uint32_t a0[4][4], a1[4][4], b0[2][4], b1[2][4];
            #pragma unroll
            for (int mi = 0; mi < 4; mi++) {
                ldmatrix_x4(a0[mi], st + OFF_A0 + aoff[mi] + ks * 32);
                if constexpr (ASPLIT)
                    ldmatrix_x4(a1[mi], st + OFF_A1 + aoff[mi] + ks * 32);
            }
            #pragma unroll
            for (int pi = 0; pi < 2; pi++) {
                ldmatrix_x4(b0[pi], st + OFF_B0 + boff[pi] + ks * 32);
                if constexpr (BSPLIT)
                    ldmatrix_x4(b1[pi], st + OFF_B1 + boff[pi] + ks * 32);
            }
            #pragma unroll
            for (int mi = 0; mi < 4; mi++) {
                #pragma unroll
                for (int ni = 0; ni < 4; ni++) {
                    const int pi = ni >> 1;
                    const int sel = (ni & 1) * 2;
                    uint32_t bh[2] = {b0[pi][sel], b0[pi][sel + 1]};
                    mma16<DT>(acc[mi][ni], a0[mi], bh);
                    if constexpr (ASPLIT)
                        mma16<DT>(acc[mi][ni], a1[mi], bh);
                    if constexpr (BSPLIT) {
                        uint32_t bl[2] = {b1[pi][sel], b1[pi][sel + 1]};
                        mma16<DT>(acc[mi][ni], a0[mi], bl);
                    }
                }
            }
        }
        __syncthreads();
    }

    // epilogue
    #pragma unroll
    for (int mi = 0; mi < 4; mi++) {
        const int row = bm + warp_m * 64 + mi * 16 + (lane >> 2);
        #pragma unroll
        for (int ni = 0; ni < 4; ni++) {
            const int col = bn + warp_n * 32 + ni * 8 + (lane & 3) * 2;
            float* acc4 = acc[mi][ni];
            if constexpr (EPI == 0) {
                *(float2*)(C + (size_t)row * ldc + col) = make_float2(acc4[0], acc4[1]);
                *(float2*)(C + (size_t)(row + 8) * ldc + col) = make_float2(acc4[2], acc4[3]);
            } else if constexpr (EPI == 1) {
                float b0v = bias[col], b1v = bias[col + 1];
                *(float2*)(C + (size_t)row * ldc + col) =
                    make_float2(softplusf(acc4[0] + b0v), softplusf(acc4[1] + b1v));
                *(float2*)(C + (size_t)(row + 8) * ldc + col) =
                    make_float2(softplusf(acc4[2] + b0v), softplusf(acc4[3] + b1v));
            } else {
                if (col < n_real) {   // col even, n_real even -> covers col+1
                    atomicAdd(&C[(size_t)row * ldc + col],       acc4[0]);
                    atomicAdd(&C[(size_t)row * ldc + col + 1],   acc4[1]);
                    atomicAdd(&C[(size_t)(row + 8) * ldc + col],     acc4[2]);
                    atomicAdd(&C[(size_t)(row + 8) * ldc + col + 1], acc4[3]);
                }
            }
        }
    }
}

// ---------------------------------------------------------------------------
// Launch. Inputs: x, h, W_xproj, W_dt, b_dt, A_log, D, W_out.
// Output: [y (1024*4096), h_new (1024*4096*16)].
// Side stream runs ALL weight prep ordered by when the main path needs it:
// wxproj+zero (G1) -> W_dt (G2) -> W_out (G3). Main runs only the x-split
// before G1.
// ---------------------------------------------------------------------------
extern "C" void kernel_launch(void* const* d_in, const int* in_sizes, int n_in,
                              void* d_out, int out_size)
{
    const float* x    = (const float*)d_in[0];
    const float* h    = (const float*)d_in[1];
    const float* Wxp  = (const float*)d_in[2];
    const float* Wdt  = (const float*)d_in[3];
    const float* bdt  = (const float*)d_in[4];
    const float* Alog = (const float*)d_in[5];
    const float* Dv   = (const float*)d_in[6];
    const float* Wout = (const float*)d_in[7];

    float* y_out    = (float*)d_out;
    float* hnew_out = y_out + (size_t)BATCH * D_MODEL;

    float *xp_p, *delta_p;
    uint16_t *Wh16_p, *Yh_p, *xh_p, *xl_p, *Wxh_p, *Wxl_p, *dh_p, *dl_p, *Wdh_p, *Wdl_p;
    cudaGetSymbolAddress((void**)&xp_p, g_xp);
    cudaGetSymbolAddress((void**)&delta_p, g_delta);
    cudaGetSymbolAddress((void**)&Wh16_p, g_Wh16);
    cudaGetSymbolAddress((void**)&Yh_p, g_Yh);
    cudaGetSymbolAddress((void**)&xh_p, g_xh);
    cudaGetSymbolAddress((void**)&xl_p, g_xl);
    cudaGetSymbolAddress((void**)&Wxh_p, g_Wxh);
    cudaGetSymbolAddress((void**)&Wxl_p, g_Wxl);
    cudaGetSymbolAddress((void**)&dh_p, g_dh);
    cudaGetSymbolAddress((void**)&dl_p, g_dl);
    cudaGetSymbolAddress((void**)&Wdh_p, g_Wdh);
    cudaGetSymbolAddress((void**)&Wdl_p, g_Wdl);

    // One-time host-object creation (no device memory; identical GPU work per call)
    static cudaStream_t s_side = nullptr;
    static cudaEvent_t eFork = nullptr, eWx = nullptr, eWdt = nullptr, eWout = nullptr;
    if (s_side == nullptr) {
        cudaStreamCreateWithFlags(&s_side, cudaStreamNonBlocking);
        cudaEventCreateWithFlags(&eFork, cudaEventDisableTiming);
        cudaEventCreateWithFlags(&eWx, cudaEventDisableTiming);
        cudaEventCreateWithFlags(&eWdt, cudaEventDisableTiming);
        cudaEventCreateWithFlags(&eWout, cudaEventDisableTiming);
    }

    const int SMEM4 = 2 * 4 * TILE_B;   // 81920  (bf16x3: 4 tiles, 2 stages)
    const int SMEM2 = 4 * 2 * TILE_B;   // 81920  (fp16x1: 2 tiles, 4 stages)
    cudaFuncSetAttribute((const void*)gemm16<0, true, true, 2, 2, 2>,
                         cudaFuncAttributeMaxDynamicSharedMemorySize, SMEM4);
    cudaFuncSetAttribute((const void*)gemm16<0, true, true, 1, 2, 2>,
                         cudaFuncAttributeMaxDynamicSharedMemorySize, SMEM4);
    cudaFuncSetAttribute((const void*)gemm16<1, false, false, 0, 4, 2>,
                         cudaFuncAttributeMaxDynamicSharedMemorySize, SMEM2);

    // ---- fork: side stream, ordered by first use on the main path ----
    cudaEventRecord(eFork, 0);
    cudaStreamWaitEvent(s_side, eFork, 0);
    split_wxproj_zero_k<<<(unsigned)((PREP_N2 + PREP_N4) / 256), 256, 0, s_side>>>(Wxp);
    cudaEventRecord(eWx, s_side);
    split_bf16_k<<<(D_MODEL * DT_RANK) / (4 * 256), 256, 0, s_side>>>(Wdt, Wdh_p, Wdl_p);
    cudaEventRecord(eWdt, s_side);
    conv_fp16_k<<<(D_MODEL * D_MODEL) / (4 * 256), 256, 0, s_side>>>(Wout, Wh16_p);
    cudaEventRecord(eWout, s_side);

    // ---- main stream: critical path ----
    split_bf16_k<<<(BATCH * D_MODEL) / (4 * 256), 256>>>(x, xh_p, xl_p);

    // join: G1 needs wxproj split + zeroed xp
    cudaStreamWaitEvent(0, eWx, 0);

    // G1: xp = x @ W_xproj^T  (bf16x3 HMMA, split-K=16 -> 384 CTAs, occ 2)
    gemm16<0, true, true, 2, 2, 2><<<dim3(BATCH / 128, WXP_PAD / 128, 16), 256, SMEM4>>>(
        xh_p, xl_p, Wxh_p, Wxl_p, xp_p, XP_COLS, D_MODEL, (D_MODEL / 16) / 32,
        nullptr, XP_COLS);

    // delta_raw split (xp cols 0..255 -> bf16 hi/lo)
    split_xp_k<<<(BATCH * DT_RANK) / (4 * 256), 256>>>();

    // join: G2 needs W_dt split
    cudaStreamWaitEvent(0, eWdt, 0);

    // G2: delta = softplus(delta_raw @ W_dt^T + b_dt)  (bf16x3, occ 2)
    gemm16<0, true, true, 1, 2, 2><<<dim3(BATCH / 128, D_MODEL / 128, 1), 256, SMEM4>>>(
        dh_p, dl_p, Wdh_p, Wdl_p, delta_p, D_MODEL, DT_RANK, DT_RANK / 32,
        bdt, D_MODEL);

    // Standalone state update (full batch; 2 d per thread)
    state_update<<<dim3(D_MODEL / 512, BATCH), 256>>>(x, h, Alog, Dv, hnew_out);

    // join: G3 needs fp16(W_out) (long finished by now)
    cudaStreamWaitEvent(0, eWout, 0);

    // G3: y = fp16(ypre) @ fp16(W_out)^T  (single product, 4-stage, occ 2)
    gemm16<1, false, false, 0, 4, 2><<<dim3(BATCH / 128, D_MODEL / 128, 1), 256, SMEM2>>>(
        Yh_p, nullptr, Wh16_p, nullptr, y_out, D_MODEL, D_MODEL, D_MODEL / 32,
        nullptr, D_MODEL);
}

// round 16
// speedup vs baseline: 1.1396x; 1.1305x over previous
#include <cuda_runtime.h>
#include <cuda_bf16.h>
#include <cuda_fp16.h>
#include <math.h>
#include <stdint.h>

#define BATCH   1024
#define D_MODEL 4096
#define D_STATE 16
#define DT_RANK 256
#define XP_COLS (DT_RANK + 2 * D_STATE)   // 288
#define WXP_PAD 384                        // 288 padded to 3 x 128

// ---------------- scratch (allocation-free rule: __device__ globals) --------
__device__ float g_xp[BATCH * XP_COLS];
__device__ float g_delta[BATCH * D_MODEL];
__device__ uint16_t g_Wh16[(size_t)D_MODEL * D_MODEL];   // fp16(W_out)
__device__ uint16_t g_Yh[(size_t)BATCH * D_MODEL];       // fp16(ypre)
__device__ uint16_t g_xh[(size_t)BATCH * D_MODEL];       // fp16(x) single
__device__ uint16_t g_Wxh[(size_t)WXP_PAD * D_MODEL];    // fp16 hi(W_xproj), padded
__device__ uint16_t g_Wxl[(size_t)WXP_PAD * D_MODEL];    // fp16 lo(W_xproj)
__device__ uint16_t g_dh[(size_t)BATCH * DT_RANK];       // fp16(delta_raw) single
__device__ uint16_t g_Wdh[(size_t)D_MODEL * DT_RANK];    // fp16 hi(W_dt)
__device__ uint16_t g_Wdl[(size_t)D_MODEL * DT_RANK];    // fp16 lo(W_dt)

__device__ __forceinline__ float softplusf(float z) {
    return (z > 20.0f) ? z : log1pf(__expf(z));
}

// ---------------- PTX helpers (sm_80-class only; no 'a'-target features) ----
__device__ __forceinline__ uint32_t smem_u32(const void* p) {
    uint32_t a;
    asm("{ .reg .u64 t; cvta.to.shared.u64 t, %1; cvt.u32.u64 %0, t; }" : "=r"(a) : "l"(p));
    return a;
}
__device__ __forceinline__ void cpasync16(uint32_t dst, const void* src) {
    asm volatile("cp.async.cg.shared.global [%0], [%1], 16;" :: "r"(dst), "l"(src));
}
__device__ __forceinline__ void cpasync_commit() {
    asm volatile("cp.async.commit_group;" ::: "memory");
}
__device__ __forceinline__ void ldmatrix_x4(uint32_t* r, uint32_t addr) {
    asm volatile("ldmatrix.sync.aligned.m8n8.x4.shared.b16 {%0,%1,%2,%3}, [%4];"
                 : "=r"(r[0]), "=r"(r[1]), "=r"(r[2]), "=r"(r[3]) : "r"(addr));
}
// DT: 0 = bf16, 1 = fp16
template<int DT>
__device__ __forceinline__ void mma16(float* c, const uint32_t* a, const uint32_t* b) {
    if constexpr (DT == 0) {
        asm volatile(
            "mma.sync.aligned.m16n8k16.row.col.f32.bf16.bf16.f32 "
            "{%0,%1,%2,%3}, {%4,%5,%6,%7}, {%8,%9}, {%0,%1,%2,%3};"
            : "+f"(c[0]), "+f"(c[1]), "+f"(c[2]), "+f"(c[3])
            : "r"(a[0]), "r"(a[1]), "r"(a[2]), "r"(a[3]), "r"(b[0]), "r"(b[1]));
    } else {
        asm volatile(
            "mma.sync.aligned.m16n8k16.row.col.f32.f16.f16.f32 "
            "{%0,%1,%2,%3}, {%4,%5,%6,%7}, {%8,%9}, {%0,%1,%2,%3};"
            : "+f"(c[0]), "+f"(c[1]), "+f"(c[2]), "+f"(c[3])
            : "r"(a[0]), "r"(a[1]), "r"(a[2]), "r"(a[3]), "r"(b[0]), "r"(b[1]));
    }
}

// ---------------------------------------------------------------------------
// Conversion / split kernels
// ---------------------------------------------------------------------------
__device__ __forceinline__ void split4_fp16(const float* vv, uint16_t* h, uint16_t* l, size_t i) {
    #pragma unroll
    for (int q = 0; q < 4; q++) {
        __half hi = __float2half_rn(vv[q]);
        __half lo = __float2half_rn(vv[q] - __half2float(hi));
        h[i + q] = *(uint16_t*)&hi;
        l[i + q] = *(uint16_t*)&lo;
    }
}

// fp32 -> fp16 hi/lo (W_dt)
__global__ void __launch_bounds__(256)
split_fp16_k(const float* __restrict__ in, uint16_t* __restrict__ h, uint16_t* __restrict__ l) {
    size_t i = ((size_t)blockIdx.x * blockDim.x + threadIdx.x) * 4;
    float4 v = *(const float4*)(in + i);
    float vv[4] = {v.x, v.y, v.z, v.w};
    split4_fp16(vv, h, l, i);
}

// fp32 -> fp16 single
__global__ void __launch_bounds__(256)
conv_fp16_k(const float* __restrict__ in, uint16_t* __restrict__ out) {
    size_t i = ((size_t)blockIdx.x * blockDim.x + threadIdx.x) * 4;
    float4 v = *(const float4*)(in + i);
    __half h0 = __float2half_rn(v.x), h1 = __float2half_rn(v.y);
    __half h2 = __float2half_rn(v.z), h3 = __float2half_rn(v.w);
    uint16_t* o = out + i;
    o[0] = *(uint16_t*)&h0; o[1] = *(uint16_t*)&h1;
    o[2] = *(uint16_t*)&h2; o[3] = *(uint16_t*)&h3;
}

// W_xproj fp16 split (padded to 384 rows) + zero of g_xp, one launch.
#define PREP_N2 ((size_t)WXP_PAD * D_MODEL / 4)     // 393216
#define PREP_N4 ((size_t)BATCH * XP_COLS / 4)       // 73728
__global__ void __launch_bounds__(256)
split_wxproj_zero_k(const float* __restrict__ in) {
    size_t gid = (size_t)blockIdx.x * 256 + threadIdx.x;
    if (gid < PREP_N2) {
        size_t i = gid * 4;
        int row = (int)(i >> 12);
        float vv[4] = {0.f, 0.f, 0.f, 0.f};
        if (row < XP_COLS) {
            float4 v = *(const float4*)(in + i);
            vv[0] = v.x; vv[1] = v.y; vv[2] = v.z; vv[3] = v.w;
        }
        split4_fp16(vv, g_Wxh, g_Wxl, i);
    } else {
        size_t i = (gid - PREP_N2) * 4;
        *(float4*)(g_xp + i) = make_float4(0.f, 0.f, 0.f, 0.f);
    }
}

// xp cols [0,256) -> fp16 single (delta_raw operand; after G1)
__global__ void __launch_bounds__(256)
split_xp_k() {
    size_t i = ((size_t)blockIdx.x * blockDim.x + threadIdx.x) * 4;   // over 1024*256
    int row = (int)(i >> 8);
    int col = (int)(i & 255);
    float4 v = *(const float4*)(g_xp + (size_t)row * XP_COLS + col);
    __half h0 = __float2half_rn(v.x), h1 = __float2half_rn(v.y);
    __half h2 = __float2half_rn(v.z), h3 = __float2half_rn(v.w);
    uint16_t* o = g_dh + i;
    o[0] = *(uint16_t*)&h0; o[1] = *(uint16_t*)&h1;
    o[2] = *(uint16_t*)&h2; o[3] = *(uint16_t*)&h3;
}

// ---------------------------------------------------------------------------
// Standalone fused state update (2 d per thread, MLP 8; full batch).
// ---------------------------------------------------------------------------
__global__ void __launch_bounds__(256)
state_update(const float* __restrict__ x,
             const float* __restrict__ h,
             const float* __restrict__ A_log,
             const float* __restrict__ Dv,
             float* __restrict__ h_new)
{
    __shared__ float sA[D_STATE], sB[D_STATE], sC[D_STATE];
    const int b = blockIdx.y;
    const int d0 = blockIdx.x * 512 + threadIdx.x;

    if (threadIdx.x < D_STATE) {
        int n = threadIdx.x;
        sA[n] = -expf(A_log[n]);
        sB[n] = g_xp[(size_t)b * XP_COLS + DT_RANK + n];
        sC[n] = g_xp[(size_t)b * XP_COLS + DT_RANK + D_STATE + n];
    }
    __syncthreads();

    const size_t bd0 = (size_t)b * D_MODEL + d0;
    const size_t bd1 = bd0 + 256;

    const float delta0 = g_delta[bd0];
    const float delta1 = g_delta[bd1];
    const float xv0 = x[bd0];
    const float xv1 = x[bd1];
    const float Dv0 = Dv[d0];
    const float Dv1 = Dv[d0 + 256];

    const float4* hp0 = (const float4*)(h + bd0 * D_STATE);
    const float4* hp1 = (const float4*)(h + bd1 * D_STATE);
    float4 hv0[4], hv1[4];
    #pragma unroll
    for (int q = 0; q < 4; q++) hv0[q] = hp0[q];
    #pragma unroll
    for (int q = 0; q < 4; q++) hv1[q] = hp1[q];

    float4* hop0 = (float4*)(h_new + bd0 * D_STATE);
    float4* hop1 = (float4*)(h_new + bd1 * D_STATE);

    const float dx0 = delta0 * xv0;
    const float dx1 = delta1 * xv1;
    float acc0 = 0.0f, acc1 = 0.0f;
    #pragma unroll
    for (int q = 0; q < 4; q++) {
        float a0 = sA[4 * q + 0], a1 = sA[4 * q + 1], a2 = sA[4 * q + 2], a3 = sA[4 * q + 3];
        float B0 = sB[4 * q + 0], B1 = sB[4 * q + 1], B2 = sB[4 * q + 2], B3 = sB[4 * q + 3];
        float C0 = sC[4 * q + 0], C1 = sC[4 * q + 1], C2 = sC[4 * q + 2], C3 = sC[4 * q + 3];

        float u0 = __expf(delta0 * a0) * hv0[q].x + dx0 * B0;
        float u1 = __expf(delta0 * a1) * hv0[q].y + dx0 * B1;
        float u2 = __expf(delta0 * a2) * hv0[q].z + dx0 * B2;
        float u3 = __expf(delta0 * a3) * hv0[q].w + dx0 * B3;
        acc0 += C0 * u0 + C1 * u1 + C2 * u2 + C3 * u3;
        hop0[q] = make_float4(u0, u1, u2, u3);

        float w0 = __expf(delta1 * a0) * hv1[q].x + dx1 * B0;
        float w1 = __expf(delta1 * a1) * hv1[q].y + dx1 * B1;
        float w2 = __expf(delta1 * a2) * hv1[q].z + dx1 * B2;
        float w3 = __expf(delta1 * a3) * hv1[q].w + dx1 * B3;
        acc1 += C0 * w0 + C1 * w1 + C2 * w2 + C3 * w3;
        hop1[q] = make_float4(w0, w1, w2, w3);
    }
    float yp0 = acc0 + Dv0 * xv0;
    float yp1 = acc1 + Dv1 * xv1;
    __half hh0 = __float2half_rn(yp0);
    __half hh1 = __float2half_rn(yp1);
    g_Yh[bd0] = *(uint16_t*)&hh0;
    g_Yh[bd1] = *(uint16_t*)&hh1;
}

// ---------------------------------------------------------------------------
// Unified HMMA GEMM.
//   ASPLIT: A = Ah + Al (a1*b0 product). BSPLIT: adds a0*b1 product.
//   Products: a0*b0 always; + a1*b0 if ASPLIT; + a0*b1 if BSPLIT.
// CTA 128x128, BK=32, 8 warps (2Mx4N), warp tile 64x32. 80B-padded SMEM rows.
// EPI: 0 = plain store, 1 = softplus(acc+bias[col]) store, 2 = guarded atomicAdd.
// OCC: min blocks/SM.
// ---------------------------------------------------------------------------
#define ROW_B 80
#define TILE_B (128 * ROW_B)          // 10240

template<int DT, bool ASPLIT, bool BSPLIT, int EPI, int NSTAGE, int OCC>
__global__ void __launch_bounds__(256, OCC)
gemm16(const uint16_t* __restrict__ Ah, const uint16_t* __restrict__ Al,
       const uint16_t* __restrict__ Bh, const uint16_t* __restrict__ Bl,
       float* __restrict__ C, int ldc, int ldab, int niters,
       const float* __restrict__ bias, int n_real)
{
    constexpr int NTILES = 1 + (ASPLIT ? 1 : 0) + 1 + (BSPLIT ? 1 : 0);
    constexpr uint32_t OFF_A0 = 0;
    constexpr uint32_t OFF_A1 = ASPLIT ? TILE_B : 0;
    constexpr uint32_t OFF_B0 = (ASPLIT ? 2 : 1) * TILE_B;
    constexpr uint32_t OFF_B1 = (ASPLIT ? 3 : 2) * TILE_B;   // only if BSPLIT
    constexpr uint32_t STAGE = NTILES * TILE_B;

    extern __shared__ char smem[];
    const uint32_t sb = smem_u32(smem);
    const int tid = threadIdx.x;
    const int wid = tid >> 5;
    const int lane = tid & 31;
    const int warp_m = wid >> 2;
    const int warp_n = wid & 3;
    const int bm = blockIdx.x * 128;
    const int bn = blockIdx.y * 128;
    const int k_begin = blockIdx.z * niters * 32;

    auto load_stage = [&](uint32_t st, int k0) {
        #pragma unroll
        for (int cc = 0; cc < 2; cc++) {
            const int idx = tid + 256 * cc;
            const int row = idx >> 2;
            const int ch  = idx & 3;
            const uint32_t d = st + (uint32_t)(row * ROW_B + ch * 16);
            const int gk = k0 + ch * 8;
            cpasync16(d + OFF_A0, Ah + (size_t)(bm + row) * ldab + gk);
            if constexpr (ASPLIT)
                cpasync16(d + OFF_A1, Al + (size_t)(bm + row) * ldab + gk);
            cpasync16(d + OFF_B0, Bh + (size_t)(bn + row) * ldab + gk);
            if constexpr (BSPLIT)
                cpasync16(d + OFF_B1, Bl + (size_t)(bn + row) * ldab + gk);
        }
        cpasync_commit();
    };

    // ldmatrix per-lane byte offsets (within a tile, ks=0)
    uint32_t aoff[4], boff[2];
    #pragma unroll
    for (int mi = 0; mi < 4; mi++)
        aoff[mi] = (uint32_t)((warp_m * 64 + mi * 16 + (lane & 15)) * ROW_B + (lane >> 4) * 16);
    #pragma unroll
    for (int pi = 0; pi < 2; pi++) {
        int chunk = lane >> 3;
        int n = warp_n * 32 + pi * 16 + (chunk >> 1) * 8 + (lane & 7);
        boff[pi] = (uint32_t)(n * ROW_B + (chunk & 1) * 16);
    }

    float acc[4][4][4];
    #pragma unroll
    for (int mi = 0; mi < 4; mi++)
        #pragma unroll
        for (int ni = 0; ni < 4; ni++)
            #pragma unroll
            for (int q = 0; q < 4; q++) acc[mi][ni][q] = 0.0f;

    // prologue: stages 0..NSTAGE-2
    #pragma unroll
    for (int s = 0; s < NSTAGE - 1; s++)
        load_stage(sb + s * STAGE, k_begin + s * 32);

    for (int it = 0; it < niters; it++) {
        if (it + NSTAGE - 1 < niters)
            load_stage(sb + ((it + NSTAGE - 1) % NSTAGE) * STAGE,
                       k_begin + (it + NSTAGE - 1) * 32);
        else
            cpasync_commit();   // keep group count uniform
        asm volatile("cp.async.wait_group %0;" :: "n"(NSTAGE - 1) : "memory");
        __syncthreads();

        const uint32_t st = sb + (it % NSTAGE) * STAGE;
        #pragma unroll
        for (int ks = 0; ks < 2; ks++) {
            uint32_t a0[4][4], a1[4][4], b0[2][4], b1[2][4];
            #pragma unroll
            for (int mi = 0; mi < 4; mi++) {
                ldmatrix_x4(a0[mi], st + OFF_A0 + aoff[mi] + ks * 32);
                if constexpr (ASPLIT)
                    ldmatrix_x4(a1[mi], st + OFF_A1 + aoff[mi] + ks * 32);
            }
            #pragma unroll
            for (int pi = 0; pi < 2; pi++) {
                ldmatrix_x4(b0[pi], st + OFF_B0 + boff[pi] + ks * 32);
                if constexpr (BSPLIT)
                    ldmatrix_x4(b1[pi], st + OFF_B1 + boff[pi] + ks * 32);
            }
            #pragma unroll
            for (int mi = 0; mi < 4; mi++) {
                #pragma unroll
                for (int ni = 0; ni < 4; ni++) {
                    const int pi = ni >> 1;
                    const int sel = (ni & 1) * 2;
                    uint32_t bh[2] = {b0[pi][sel], b0[pi][sel + 1]};
                    mma16<DT>(acc[mi][ni], a0[mi], bh);
                    if constexpr (ASPLIT)
                        mma16<DT>(acc[mi][ni], a1[mi], bh);
                    if constexpr (BSPLIT) {
                        uint32_t bl[2] = {b1[pi][sel], b1[pi][sel + 1]};
                        mma16<DT>(acc[mi][ni], a0[mi], bl);
                    }
                }
            }
        }
        __syncthreads();
    }

    // epilogue
    #pragma unroll
    for (int mi = 0; mi < 4; mi++) {
        const int row = bm + warp_m * 64 + mi * 16 + (lane >> 2);
        #pragma unroll
        for (int ni = 0; ni < 4; ni++) {
            const int col = bn + warp_n * 32 + ni * 8 + (lane & 3) * 2;
            float* acc4 = acc[mi][ni];
            if constexpr (EPI == 0) {
                *(float2*)(C + (size_t)row * ldc + col) = make_float2(acc4[0], acc4[1]);
                *(float2*)(C + (size_t)(row + 8) * ldc + col) = make_float2(acc4[2], acc4[3]);
            } else if constexpr (EPI == 1) {
                float b0v = bias[col], b1v = bias[col + 1];
                *(float2*)(C + (size_t)row * ldc + col) =
                    make_float2(softplusf(acc4[0] + b0v), softplusf(acc4[1] + b1v));
                *(float2*)(C + (size_t)(row + 8) * ldc + col) =
                    make_float2(softplusf(acc4[2] + b0v), softplusf(acc4[3] + b1v));
            } else {
                if (col < n_real) {   // col even, n_real even -> covers col+1
                    atomicAdd(&C[(size_t)row * ldc + col],       acc4[0]);
                    atomicAdd(&C[(size_t)row * ldc + col + 1],   acc4[1]);
                    atomicAdd(&C[(size_t)(row + 8) * ldc + col],     acc4[2]);
                    atomicAdd(&C[(size_t)(row + 8) * ldc + col + 1], acc4[3]);
                }
            }
        }
    }
}

// ---------------------------------------------------------------------------
// Launch. Inputs: x, h, W_xproj, W_dt, b_dt, A_log, D, W_out.
// Output: [y (1024*4096), h_new (1024*4096*16)].
// ---------------------------------------------------------------------------
extern "C" void kernel_launch(void* const* d_in, const int* in_sizes, int n_in,
                              void* d_out, int out_size)
{
    const float* x    = (const float*)d_in[0];
    const float* h    = (const float*)d_in[1];
    const float* Wxp  = (const float*)d_in[2];
    const float* Wdt  = (const float*)d_in[3];
    const float* bdt  = (const float*)d_in[4];
    const float* Alog = (const float*)d_in[5];
    const float* Dv   = (const float*)d_in[6];
    const float* Wout = (const float*)d_in[7];

    float* y_out    = (float*)d_out;
    float* hnew_out = y_out + (size_t)BATCH * D_MODEL;

    float *xp_p, *delta_p;
    uint16_t *Wh16_p, *Yh_p, *xh_p, *Wxh_p, *Wxl_p, *dh_p, *Wdh_p, *Wdl_p;
    cudaGetSymbolAddress((void**)&xp_p, g_xp);
    cudaGetSymbolAddress((void**)&delta_p, g_delta);
    cudaGetSymbolAddress((void**)&Wh16_p, g_Wh16);
    cudaGetSymbolAddress((void**)&Yh_p, g_Yh);
    cudaGetSymbolAddress((void**)&xh_p, g_xh);
    cudaGetSymbolAddress((void**)&Wxh_p, g_Wxh);
    cudaGetSymbolAddress((void**)&Wxl_p, g_Wxl);
    cudaGetSymbolAddress((void**)&dh_p, g_dh);
    cudaGetSymbolAddress((void**)&Wdh_p, g_Wdh);
    cudaGetSymbolAddress((void**)&Wdl_p, g_Wdl);

    // One-time host-object creation (no device memory; identical GPU work per call)
    static cudaStream_t s_side = nullptr;
    static cudaEvent_t eFork = nullptr, eWx = nullptr, eWdt = nullptr, eWout = nullptr;
    if (s_side == nullptr) {
        cudaStreamCreateWithFlags(&s_side, cudaStreamNonBlocking);
        cudaEventCreateWithFlags(&eFork, cudaEventDisableTiming);
        cudaEventCreateWithFlags(&eWx, cudaEventDisableTiming);
        cudaEventCreateWithFlags(&eWdt, cudaEventDisableTiming);
        cudaEventCreateWithFlags(&eWout, cudaEventDisableTiming);
    }

    const int SMEM3 = 2 * 3 * TILE_B;   // 61440  (fp16 2-product: 3 tiles, 2 stages)
    const int SMEM2 = 4 * 2 * TILE_B;   // 81920  (fp16x1: 2 tiles, 4 stages)
    cudaFuncSetAttribute((const void*)gemm16<1, false, true, 2, 2, 2>,
                         cudaFuncAttributeMaxDynamicSharedMemorySize, SMEM3);
    cudaFuncSetAttribute((const void*)gemm16<1, false, true, 1, 2, 2>,
                         cudaFuncAttributeMaxDynamicSharedMemorySize, SMEM3);
    cudaFuncSetAttribute((const void*)gemm16<1, false, false, 0, 4, 2>,
                         cudaFuncAttributeMaxDynamicSharedMemorySize, SMEM2);

    // ---- fork: side stream, ordered by first use on the main path ----
    cudaEventRecord(eFork, 0);
    cudaStreamWaitEvent(s_side, eFork, 0);
    split_wxproj_zero_k<<<(unsigned)((PREP_N2 + PREP_N4) / 256), 256, 0, s_side>>>(Wxp);
    cudaEventRecord(eWx, s_side);
    split_fp16_k<<<(D_MODEL * DT_RANK) / (4 * 256), 256, 0, s_side>>>(Wdt, Wdh_p, Wdl_p);
    cudaEventRecord(eWdt, s_side);
    conv_fp16_k<<<(D_MODEL * D_MODEL) / (4 * 256), 256, 0, s_side>>>(Wout, Wh16_p);
    cudaEventRecord(eWout, s_side);

    // ---- main stream: critical path ----
    conv_fp16_k<<<(BATCH * D_MODEL) / (4 * 256), 256>>>(x, xh_p);

    // join: G1 needs wxproj split + zeroed xp
    cudaStreamWaitEvent(0, eWx, 0);

    // G1: xp = fp16(x) @ (fp16 hi/lo W_xproj)^T  (2 products, split-K=16, occ 2)
    gemm16<1, false, true, 2, 2, 2><<<dim3(BATCH / 128, WXP_PAD / 128, 16), 256, SMEM3>>>(
        xh_p, nullptr, Wxh_p, Wxl_p, xp_p, XP_COLS, D_MODEL, (D_MODEL / 16) / 32,
        nullptr, XP_COLS);

    // delta_raw -> fp16 single
    split_xp_k<<<(BATCH * DT_RANK) / (4 * 256), 256>>>();

    // join: G2 needs W_dt split
    cudaStreamWaitEvent(0, eWdt, 0);

    // G2: delta = softplus(fp16(delta_raw) @ (fp16 hi/lo W_dt)^T + b_dt)  (2 products)
    gemm16<1, false, true, 1, 2, 2><<<dim3(BATCH / 128, D_MODEL / 128, 1), 256, SMEM3>>>(
        dh_p, nullptr, Wdh_p, Wdl_p, delta_p, D_MODEL, DT_RANK, DT_RANK / 32,
        bdt, D_MODEL);

    // Standalone state update (full batch; 2 d per thread)
    state_update<<<dim3(D_MODEL / 512, BATCH), 256>>>(x, h, Alog, Dv, hnew_out);

    // join: G3 needs fp16(W_out)
    cudaStreamWaitEvent(0, eWout, 0);

    // G3: y = fp16(ypre) @ fp16(W_out)^T  (single product, 4-stage, occ 2)
    gemm16<1, false, false, 0, 4, 2><<<dim3(BATCH / 128, D_MODEL / 128, 1), 256, SMEM2>>>(
        Yh_p, nullptr, Wh16_p, nullptr, y_out, D_MODEL, D_MODEL, D_MODEL / 32,
        nullptr, D_MODEL);
}

// round 17
// speedup vs baseline: 1.1585x; 1.0166x over previous
#include <cuda_runtime.h>
#include <cuda_bf16.h>
#include <cuda_fp16.h>
#include <math.h>
#include <stdint.h>

#define BATCH   1024
#define D_MODEL 4096
#define D_STATE 16
#define DT_RANK 256
#define XP_COLS (DT_RANK + 2 * D_STATE)   // 288
#define WXP_PAD 384                        // 288 padded to 3 x 128

// ---------------- scratch (allocation-free rule: __device__ globals) --------
__device__ float g_xp[BATCH * XP_COLS];
__device__ float g_delta[BATCH * D_MODEL];
__device__ uint16_t g_Wh16[(size_t)D_MODEL * D_MODEL];   // fp16(W_out)
__device__ uint16_t g_Yh[(size_t)BATCH * D_MODEL];       // fp16(ypre)
__device__ uint16_t g_xh[(size_t)BATCH * D_MODEL];       // fp16(x)
__device__ uint16_t g_Wx16[(size_t)WXP_PAD * D_MODEL];   // fp16(W_xproj), padded
__device__ uint16_t g_dh[(size_t)BATCH * DT_RANK];       // fp16(delta_raw)
__device__ uint16_t g_Wd16[(size_t)D_MODEL * DT_RANK];   // fp16(W_dt)

__device__ __forceinline__ float softplusf(float z) {
    return (z > 20.0f) ? z : log1pf(__expf(z));
}

// ---------------- PTX helpers (sm_80-class only; no 'a'-target features) ----
__device__ __forceinline__ uint32_t smem_u32(const void* p) {
    uint32_t a;
    asm("{ .reg .u64 t; cvta.to.shared.u64 t, %1; cvt.u32.u64 %0, t; }" : "=r"(a) : "l"(p));
    return a;
}
__device__ __forceinline__ void cpasync16(uint32_t dst, const void* src) {
    asm volatile("cp.async.cg.shared.global [%0], [%1], 16;" :: "r"(dst), "l"(src));
}
__device__ __forceinline__ void cpasync_commit() {
    asm volatile("cp.async.commit_group;" ::: "memory");
}
__device__ __forceinline__ void ldmatrix_x4(uint32_t* r, uint32_t addr) {
    asm volatile("ldmatrix.sync.aligned.m8n8.x4.shared.b16 {%0,%1,%2,%3}, [%4];"
                 : "=r"(r[0]), "=r"(r[1]), "=r"(r[2]), "=r"(r[3]) : "r"(addr));
}
__device__ __forceinline__ void mma_fp16(float* c, const uint32_t* a, const uint32_t* b) {
    asm volatile(
        "mma.sync.aligned.m16n8k16.row.col.f32.f16.f16.f32 "
        "{%0,%1,%2,%3}, {%4,%5,%6,%7}, {%8,%9}, {%0,%1,%2,%3};"
        : "+f"(c[0]), "+f"(c[1]), "+f"(c[2]), "+f"(c[3])
        : "r"(a[0]), "r"(a[1]), "r"(a[2]), "r"(a[3]), "r"(b[0]), "r"(b[1]));
}

// ---------------------------------------------------------------------------
// Conversion kernels
// ---------------------------------------------------------------------------
__global__ void __launch_bounds__(256)
conv_fp16_k(const float* __restrict__ in, uint16_t* __restrict__ out) {
    size_t i = ((size_t)blockIdx.x * blockDim.x + threadIdx.x) * 4;
    float4 v = *(const float4*)(in + i);
    __half h0 = __float2half_rn(v.x), h1 = __float2half_rn(v.y);
    __half h2 = __float2half_rn(v.z), h3 = __float2half_rn(v.w);
    uint16_t* o = out + i;
    o[0] = *(uint16_t*)&h0; o[1] = *(uint16_t*)&h1;
    o[2] = *(uint16_t*)&h2; o[3] = *(uint16_t*)&h3;
}

// W_xproj fp16 conversion (padded to 384 rows) + zero of g_xp, one launch.
#define PREP_N2 ((size_t)WXP_PAD * D_MODEL / 4)     // 393216
#define PREP_N4 ((size_t)BATCH * XP_COLS / 4)       // 73728
__global__ void __launch_bounds__(256)
conv_wxproj_zero_k(const float* __restrict__ in) {
    size_t gid = (size_t)blockIdx.x * 256 + threadIdx.x;
    if (gid < PREP_N2) {
        size_t i = gid * 4;
        int row = (int)(i >> 12);
        float vv[4] = {0.f, 0.f, 0.f, 0.f};
        if (row < XP_COLS) {
            float4 v = *(const float4*)(in + i);
            vv[0] = v.x; vv[1] = v.y; vv[2] = v.z; vv[3] = v.w;
        }
        #pragma unroll
        for (int q = 0; q < 4; q++) {
            __half hv = __float2half_rn(vv[q]);
            g_Wx16[i + q] = *(uint16_t*)&hv;
        }
    } else {
        size_t i = (gid - PREP_N2) * 4;
        *(float4*)(g_xp + i) = make_float4(0.f, 0.f, 0.f, 0.f);
    }
}

// xp cols [0,256) -> fp16 (delta_raw operand; after G1)
__global__ void __launch_bounds__(256)
split_xp_k() {
    size_t i = ((size_t)blockIdx.x * blockDim.x + threadIdx.x) * 4;   // over 1024*256
    int row = (int)(i >> 8);
    int col = (int)(i & 255);
    float4 v = *(const float4*)(g_xp + (size_t)row * XP_COLS + col);
    __half h0 = __float2half_rn(v.x), h1 = __float2half_rn(v.y);
    __half h2 = __float2half_rn(v.z), h3 = __float2half_rn(v.w);
    uint16_t* o = g_dh + i;
    o[0] = *(uint16_t*)&h0; o[1] = *(uint16_t*)&h1;
    o[2] = *(uint16_t*)&h2; o[3] = *(uint16_t*)&h3;
}

// ---------------------------------------------------------------------------
// Standalone fused state update (2 d per thread, MLP 8; full batch).
// ---------------------------------------------------------------------------
__global__ void __launch_bounds__(256)
state_update(const float* __restrict__ x,
             const float* __restrict__ h,
             const float* __restrict__ A_log,
             const float* __restrict__ Dv,
             float* __restrict__ h_new)
{
    __shared__ float sA[D_STATE], sB[D_STATE], sC[D_STATE];
    const int b = blockIdx.y;
    const int d0 = blockIdx.x * 512 + threadIdx.x;

    if (threadIdx.x < D_STATE) {
        int n = threadIdx.x;
        sA[n] = -expf(A_log[n]);
        sB[n] = g_xp[(size_t)b * XP_COLS + DT_RANK + n];
        sC[n] = g_xp[(size_t)b * XP_COLS + DT_RANK + D_STATE + n];
    }
    __syncthreads();

    const size_t bd0 = (size_t)b * D_MODEL + d0;
    const size_t bd1 = bd0 + 256;

    const float delta0 = g_delta[bd0];
    const float delta1 = g_delta[bd1];
    const float xv0 = x[bd0];
    const float xv1 = x[bd1];
    const float Dv0 = Dv[d0];
    const float Dv1 = Dv[d0 + 256];

    const float4* hp0 = (const float4*)(h + bd0 * D_STATE);
    const float4* hp1 = (const float4*)(h + bd1 * D_STATE);
    float4 hv0[4], hv1[4];
    #pragma unroll
    for (int q = 0; q < 4; q++) hv0[q] = hp0[q];
    #pragma unroll
    for (int q = 0; q < 4; q++) hv1[q] = hp1[q];

    float4* hop0 = (float4*)(h_new + bd0 * D_STATE);
    float4* hop1 = (float4*)(h_new + bd1 * D_STATE);

    const float dx0 = delta0 * xv0;
    const float dx1 = delta1 * xv1;
    float acc0 = 0.0f, acc1 = 0.0f;
    #pragma unroll
    for (int q = 0; q < 4; q++) {
        float a0 = sA[4 * q + 0], a1 = sA[4 * q + 1], a2 = sA[4 * q + 2], a3 = sA[4 * q + 3];
        float B0 = sB[4 * q + 0], B1 = sB[4 * q + 1], B2 = sB[4 * q + 2], B3 = sB[4 * q + 3];
        float C0 = sC[4 * q + 0], C1 = sC[4 * q + 1], C2 = sC[4 * q + 2], C3 = sC[4 * q + 3];

        float u0 = __expf(delta0 * a0) * hv0[q].x + dx0 * B0;
        float u1 = __expf(delta0 * a1) * hv0[q].y + dx0 * B1;
        float u2 = __expf(delta0 * a2) * hv0[q].z + dx0 * B2;
        float u3 = __expf(delta0 * a3) * hv0[q].w + dx0 * B3;
        acc0 += C0 * u0 + C1 * u1 + C2 * u2 + C3 * u3;
        hop0[q] = make_float4(u0, u1, u2, u3);

        float w0 = __expf(delta1 * a0) * hv1[q].x + dx1 * B0;
        float w1 = __expf(delta1 * a1) * hv1[q].y + dx1 * B1;
        float w2 = __expf(delta1 * a2) * hv1[q].z + dx1 * B2;
        float w3 = __expf(delta1 * a3) * hv1[q].w + dx1 * B3;
        acc1 += C0 * w0 + C1 * w1 + C2 * w2 + C3 * w3;
        hop1[q] = make_float4(w0, w1, w2, w3);
    }
    float yp0 = acc0 + Dv0 * xv0;
    float yp1 = acc1 + Dv1 * xv1;
    __half hh0 = __float2half_rn(yp0);
    __half hh1 = __float2half_rn(yp1);
    g_Yh[bd0] = *(uint16_t*)&hh0;
    g_Yh[bd1] = *(uint16_t*)&hh1;
}

// ---------------------------------------------------------------------------
// fp16 single-product HMMA GEMM: C[m,n] (+)= sum_k A[m,k]*B[n,k].
// CTA 128x128, BK=32, 8 warps (2Mx4N), warp tile 64x32. 80B-padded SMEM rows.
// EPI: 0 = plain store, 1 = softplus(acc+bias[col]) store, 2 = guarded atomicAdd.
// 4-stage cp.async pipeline, occ 2 (<=128 regs, single wave).
// ---------------------------------------------------------------------------
#define ROW_B 80
#define TILE_B (128 * ROW_B)          // 10240
#define NSTAGE 4
#define STAGE_B (2 * TILE_B)          // 20480
#define SMEM_G (NSTAGE * STAGE_B)     // 81920
#define OFF_B0 TILE_B

template<int EPI>
__global__ void __launch_bounds__(256, 2)
gemm16(const uint16_t* __restrict__ Ah, const uint16_t* __restrict__ Bh,
       float* __restrict__ C, int ldc, int ldab, int niters,
       const float* __restrict__ bias, int n_real)
{
    extern __shared__ char smem[];
    const uint32_t sb = smem_u32(smem);
    const int tid = threadIdx.x;
    const int wid = tid >> 5;
    const int lane = tid & 31;
    const int warp_m = wid >> 2;
    const int warp_n = wid & 3;
    const int bm = blockIdx.x * 128;
    const int bn = blockIdx.y * 128;
    const int k_begin = blockIdx.z * niters * 32;

    auto load_stage = [&](uint32_t st, int k0) {
        #pragma unroll
        for (int cc = 0; cc < 2; cc++) {
            const int idx = tid + 256 * cc;
            const int row = idx >> 2;
            const int ch  = idx & 3;
            const uint32_t d = st + (uint32_t)(row * ROW_B + ch * 16);
            const int gk = k0 + ch * 8;
            cpasync16(d, Ah + (size_t)(bm + row) * ldab + gk);
            cpasync16(d + OFF_B0, Bh + (size_t)(bn + row) * ldab + gk);
        }
        cpasync_commit();
    };

    // ldmatrix per-lane byte offsets (within a tile, ks=0)
    uint32_t aoff[4], boff[2];
    #pragma unroll
    for (int mi = 0; mi < 4; mi++)
        aoff[mi] = (uint32_t)((warp_m * 64 + mi * 16 + (lane & 15)) * ROW_B + (lane >> 4) * 16);
    #pragma unroll
    for (int pi = 0; pi < 2; pi++) {
        int chunk = lane >> 3;
        int n = warp_n * 32 + pi * 16 + (chunk >> 1) * 8 + (lane & 7);
        boff[pi] = (uint32_t)(n * ROW_B + (chunk & 1) * 16);
    }

    float acc[4][4][4];
    #pragma unroll
    for (int mi = 0; mi < 4; mi++)
        #pragma unroll
        for (int ni = 0; ni < 4; ni++)
            #pragma unroll
            for (int q = 0; q < 4; q++) acc[mi][ni][q] = 0.0f;

    // prologue: stages 0..NSTAGE-2
    #pragma unroll
    for (int s = 0; s < NSTAGE - 1; s++)
        load_stage(sb + s * STAGE_B, k_begin + s * 32);

    for (int it = 0; it < niters; it++) {
        if (it + NSTAGE - 1 < niters)
            load_stage(sb + ((it + NSTAGE - 1) % NSTAGE) * STAGE_B,
                       k_begin + (it + NSTAGE - 1) * 32);
        else
            cpasync_commit();   // keep group count uniform
        asm volatile("cp.async.wait_group %0;" :: "n"(NSTAGE - 1) : "memory");
        __syncthreads();

        const uint32_t st = sb + (it % NSTAGE) * STAGE_B;
        #pragma unroll
        for (int ks = 0; ks < 2; ks++) {
            uint32_t a0[4][4], b0[2][4];
            #pragma unroll
            for (int mi = 0; mi < 4; mi++)
                ldmatrix_x4(a0[mi], st + aoff[mi] + ks * 32);
            #pragma unroll
            for (int pi = 0; pi < 2; pi++)
                ldmatrix_x4(b0[pi], st + OFF_B0 + boff[pi] + ks * 32);
            #pragma unroll
            for (int mi = 0; mi < 4; mi++) {
                #pragma unroll
                for (int ni = 0; ni < 4; ni++) {
                    const int pi = ni >> 1;
                    const int sel = (ni & 1) * 2;
                    uint32_t bh[2] = {b0[pi][sel], b0[pi][sel + 1]};
                    mma_fp16(acc[mi][ni], a0[mi], bh);
                }
            }
        }
        __syncthreads();
    }

    // epilogue
    #pragma unroll
    for (int mi = 0; mi < 4; mi++) {
        const int row = bm + warp_m * 64 + mi * 16 + (lane >> 2);
        #pragma unroll
        for (int ni = 0; ni < 4; ni++) {
            const int col = bn + warp_n * 32 + ni * 8 + (lane & 3) * 2;
            float* acc4 = acc[mi][ni];
            if constexpr (EPI == 0) {
                *(float2*)(C + (size_t)row * ldc + col) = make_float2(acc4[0], acc4[1]);
                *(float2*)(C + (size_t)(row + 8) * ldc + col) = make_float2(acc4[2], acc4[3]);
            } else if constexpr (EPI == 1) {
                float b0v = bias[col], b1v = bias[col + 1];
                *(float2*)(C + (size_t)row * ldc + col) =
                    make_float2(softplusf(acc4[0] + b0v), softplusf(acc4[1] + b1v));
                *(float2*)(C + (size_t)(row + 8) * ldc + col) =
                    make_float2(softplusf(acc4[2] + b0v), softplusf(acc4[3] + b1v));
            } else {
                if (col < n_real) {   // col even, n_real even -> covers col+1
                    atomicAdd(&C[(size_t)row * ldc + col],       acc4[0]);
                    atomicAdd(&C[(size_t)row * ldc + col + 1],   acc4[1]);
                    atomicAdd(&C[(size_t)(row + 8) * ldc + col],     acc4[2]);
                    atomicAdd(&C[(size_t)(row + 8) * ldc + col + 1], acc4[3]);
                }
            }
        }
    }
}

// ---------------------------------------------------------------------------
// Launch. Inputs: x, h, W_xproj, W_dt, b_dt, A_log, D, W_out.
// Output: [y (1024*4096), h_new (1024*4096*16)].
// ---------------------------------------------------------------------------
extern "C" void kernel_launch(void* const* d_in, const int* in_sizes, int n_in,
                              void* d_out, int out_size)
{
    const float* x    = (const float*)d_in[0];
    const float* h    = (const float*)d_in[1];
    const float* Wxp  = (const float*)d_in[2];
    const float* Wdt  = (const float*)d_in[3];
    const float* bdt  = (const float*)d_in[4];
    const float* Alog = (const float*)d_in[5];
    const float* Dv   = (const float*)d_in[6];
    const float* Wout = (const float*)d_in[7];

    float* y_out    = (float*)d_out;
    float* hnew_out = y_out + (size_t)BATCH * D_MODEL;

    float *xp_p, *delta_p;
    uint16_t *Wh16_p, *Yh_p, *xh_p, *Wx16_p, *dh_p, *Wd16_p;
    cudaGetSymbolAddress((void**)&xp_p, g_xp);
    cudaGetSymbolAddress((void**)&delta_p, g_delta);
    cudaGetSymbolAddress((void**)&Wh16_p, g_Wh16);
    cudaGetSymbolAddress((void**)&Yh_p, g_Yh);
    cudaGetSymbolAddress((void**)&xh_p, g_xh);
    cudaGetSymbolAddress((void**)&Wx16_p, g_Wx16);
    cudaGetSymbolAddress((void**)&dh_p, g_dh);
    cudaGetSymbolAddress((void**)&Wd16_p, g_Wd16);

    // One-time host-object creation (no device memory; identical GPU work per call)
    static cudaStream_t s_side = nullptr;
    static cudaEvent_t eFork = nullptr, eWx = nullptr, eWdt = nullptr, eWout = nullptr;
    if (s_side == nullptr) {
        cudaStreamCreateWithFlags(&s_side, cudaStreamNonBlocking);
        cudaEventCreateWithFlags(&eFork, cudaEventDisableTiming);
        cudaEventCreateWithFlags(&eWx, cudaEventDisableTiming);
        cudaEventCreateWithFlags(&eWdt, cudaEventDisableTiming);
        cudaEventCreateWithFlags(&eWout, cudaEventDisableTiming);
    }

    cudaFuncSetAttribute((const void*)gemm16<0>,
                         cudaFuncAttributeMaxDynamicSharedMemorySize, SMEM_G);
    cudaFuncSetAttribute((const void*)gemm16<1>,
                         cudaFuncAttributeMaxDynamicSharedMemorySize, SMEM_G);
    cudaFuncSetAttribute((const void*)gemm16<2>,
                         cudaFuncAttributeMaxDynamicSharedMemorySize, SMEM_G);

    // ---- fork: side stream, ordered by first use on the main path ----
    cudaEventRecord(eFork, 0);
    cudaStreamWaitEvent(s_side, eFork, 0);
    conv_wxproj_zero_k<<<(unsigned)((PREP_N2 + PREP_N4) / 256), 256, 0, s_side>>>(Wxp);
    cudaEventRecord(eWx, s_side);
    conv_fp16_k<<<(D_MODEL * DT_RANK) / (4 * 256), 256, 0, s_side>>>(Wdt, Wd16_p);
    cudaEventRecord(eWdt, s_side);
    conv_fp16_k<<<(D_MODEL * D_MODEL) / (4 * 256), 256, 0, s_side>>>(Wout, Wh16_p);
    cudaEventRecord(eWout, s_side);

    // ---- main stream: critical path ----
    conv_fp16_k<<<(BATCH * D_MODEL) / (4 * 256), 256>>>(x, xh_p);

    // join: G1 needs fp16(W_xproj) + zeroed xp
    cudaStreamWaitEvent(0, eWx, 0);

    // G1: xp = fp16(x) @ fp16(W_xproj)^T  (1 product, split-K=16, occ 2)
    gemm16<2><<<dim3(BATCH / 128, WXP_PAD / 128, 16), 256, SMEM_G>>>(
        xh_p, Wx16_p, xp_p, XP_COLS, D_MODEL, (D_MODEL / 16) / 32,
        nullptr, XP_COLS);

    // delta_raw -> fp16
    split_xp_k<<<(BATCH * DT_RANK) / (4 * 256), 256>>>();

    // join: G2 needs fp16(W_dt)
    cudaStreamWaitEvent(0, eWdt, 0);

    // G2: delta = softplus(fp16(delta_raw) @ fp16(W_dt)^T + b_dt)  (1 product)
    gemm16<1><<<dim3(BATCH / 128, D_MODEL / 128, 1), 256, SMEM_G>>>(
        dh_p, Wd16_p, delta_p, D_MODEL, DT_RANK, DT_RANK / 32,
        bdt, D_MODEL);

    // Standalone state update (full batch; 2 d per thread)
    state_update<<<dim3(D_MODEL / 512, BATCH), 256>>>(x, h, Alog, Dv, hnew_out);

    // join: G3 needs fp16(W_out)
    cudaStreamWaitEvent(0, eWout, 0);

    // G3: y = fp16(ypre) @ fp16(W_out)^T  (1 product)
    gemm16<0><<<dim3(BATCH / 128, D_MODEL / 128, 1), 256, SMEM_G>>>(
        Yh_p, Wh16_p, y_out, D_MODEL, D_MODEL, D_MODEL / 32,
        nullptr, D_MODEL);
}